// round 13
// baseline (speedup 1.0000x reference)
#include <cuda_runtime.h>
#include <cuda_fp16.h>
#include <cstdint>

#define CB   128
#define CN1  256
#define CN2  256
#define CD   256
#define CH   8
#define CDH  32
#define CDFF 1024

// ---------------- scratch (device globals) ----------------
__device__ __half g_wqkvT[768 * CD];      // [N][K] half, q-part pre-scaled
__device__ __half g_woT  [CD * CD];
__device__ __half g_w1T  [CDFF * CD];
__device__ __half g_w2T  [CD * CDFF];
__device__ float  g_bqkv [768];
__device__ __half g_x1h  [CB * CN1 * CD];
__device__ __half g_x2h  [CB * CN2 * CD];
__device__ __half g_qkv  [CB * CN1 * 768];
__device__ __half g_kv2  [CB * CN2 * 512];
__device__ __half g_ctx  [CB * CN1 * CD];
__device__ float  g_tmp  [CB * CN1 * CD];
__device__ float  g_o1f  [CB * CN1 * CD];
__device__ __half g_o1h  [CB * CN1 * CD];
__device__ __half g_hid  [CB * CN1 * CDFF];
__device__ uint32_t g_bm1[CB * CN1 * 8];
__device__ uint32_t g_bm2[CB * 8];

#define QSCALE (0.17677669529663687f * 1.4426950408889634f)

// ---------------- helpers ----------------
__device__ __forceinline__ void cp16(void* s, const void* g) {
    unsigned sa = (unsigned)__cvta_generic_to_shared(s);
    asm volatile("cp.async.cg.shared.global [%0], [%1], 16;\n" :: "r"(sa), "l"(g));
}
__device__ __forceinline__ void cp_commit() { asm volatile("cp.async.commit_group;\n"); }
template <int N> __device__ __forceinline__ void cp_wait() {
    asm volatile("cp.async.wait_group %0;\n" :: "n"(N));
}
__device__ __forceinline__ void mma16816(float* d, const uint32_t* a, const uint32_t* b) {
    asm volatile(
        "mma.sync.aligned.m16n8k16.row.col.f32.f16.f16.f32 "
        "{%0,%1,%2,%3}, {%4,%5,%6,%7}, {%8,%9}, {%0,%1,%2,%3};"
        : "+f"(d[0]), "+f"(d[1]), "+f"(d[2]), "+f"(d[3])
        : "r"(a[0]), "r"(a[1]), "r"(a[2]), "r"(a[3]), "r"(b[0]), "r"(b[1]));
}
__device__ __forceinline__ void ldsm4(uint32_t* r, const __half* p) {
    uint32_t a = (uint32_t)__cvta_generic_to_shared(p);
    asm volatile("ldmatrix.sync.aligned.m8n8.x4.shared.b16 {%0,%1,%2,%3}, [%4];"
                 : "=r"(r[0]), "=r"(r[1]), "=r"(r[2]), "=r"(r[3]) : "r"(a));
}
__device__ __forceinline__ void ldsm4t(uint32_t* r, const __half* p) {
    uint32_t a = (uint32_t)__cvta_generic_to_shared(p);
    asm volatile("ldmatrix.sync.aligned.m8n8.x4.trans.shared.b16 {%0,%1,%2,%3}, [%4];"
                 : "=r"(r[0]), "=r"(r[1]), "=r"(r[2]), "=r"(r[3]) : "r"(a));
}
__device__ __forceinline__ float ex2f(float x) {
    float y; asm("ex2.approx.f32 %0, %1;" : "=f"(y) : "f"(x)); return y;
}
__device__ __forceinline__ uint32_t f22u(float a, float b) {
    __half2 h = __floats2half2_rn(a, b);
    return *(uint32_t*)&h;
}

// ============================================================================
// fp16 GEMM body: block 128x256x32, 8 warps (2m x 4n), warp tile 64x64
// (per-warp mainloop identical to the proven R7 config), m16n8k16, ldmatrix,
// 4-stage cp.async, runtime N/K.
// ============================================================================
#define BM 128
#define BN 256
#define BK 32
#define APADH 40
#define STGH ((128 + 256) * APADH)               // A rows + B rows per stage
#define GS 4
#define GSMEM_BYTES (GS * STGH * 2)               // 122880

template <int EPI, int OUTH>
__device__ __forceinline__ void gemm_body(
    const __half* __restrict__ A, const __half* __restrict__ WT,
    const float* __restrict__ bias, void* __restrict__ Cv,
    __half* smh, int m0, int n0, int N, int K, int tid)
{
    const int warp = tid >> 5;
    const int lane = tid & 31;
    const int wm   = warp & 1;           // row half: wm*64
    const int wn   = warp >> 1;          // col quarter: wn*64 (0..3)
    const int kt   = K / BK;
    const int qr   = lane >> 2;
    const int qc   = lane & 3;
    const int arow = (lane & 7) + 8 * ((lane >> 3) & 1);
    const int acol = 8 * (lane >> 4);
    const int brow = (lane & 7) + 8 * (lane >> 4);
    const int bcol = 8 * ((lane >> 3) & 1);

    auto loadStage = [&](int t) {
        __half* As = smh + (t & (GS - 1)) * STGH;
        __half* Bs = As + 128 * APADH;
        const int k0 = t * BK;
#pragma unroll
        for (int j = 0; j < 2; j++) {               // 512 16B-chunks of A
            int i = tid + j * 256;
            int r = i >> 2, c8 = (i & 3) * 8;
            cp16(As + r * APADH + c8, A + (size_t)(m0 + r) * K + k0 + c8);
        }
#pragma unroll
        for (int j = 0; j < 4; j++) {               // 1024 16B-chunks of B
            int i = tid + j * 256;
            int r = i >> 2, c8 = (i & 3) * 8;
            cp16(Bs + r * APADH + c8, WT + (size_t)(n0 + r) * K + k0 + c8);
        }
        cp_commit();
    };

    float acc[4][8][4];
#pragma unroll
    for (int mt = 0; mt < 4; mt++)
#pragma unroll
        for (int nt = 0; nt < 8; nt++)
#pragma unroll
            for (int e = 0; e < 4; e++) acc[mt][nt][e] = 0.0f;

    loadStage(0);
    loadStage(1);
    loadStage(2);

    for (int t = 0; t < kt; t++) {
        if (t + 2 < kt)      cp_wait<2>();
        else if (t + 1 < kt) cp_wait<1>();
        else                 cp_wait<0>();
        __syncthreads();
        if (t + 3 < kt) loadStage(t + 3);

        const __half* As = smh + (t & (GS - 1)) * STGH + (wm * 64) * APADH;
        const __half* Bs = smh + (t & (GS - 1)) * STGH + 128 * APADH + (wn * 64) * APADH;
#pragma unroll
        for (int kk = 0; kk < BK; kk += 16) {
            uint32_t af[4][4];
            uint32_t bf[4][4];
#pragma unroll
            for (int mt = 0; mt < 4; mt++)
                ldsm4(af[mt], As + (mt * 16 + arow) * APADH + kk + acol);
#pragma unroll
            for (int p = 0; p < 4; p++)
                ldsm4(bf[p], Bs + (p * 16 + brow) * APADH + kk + bcol);
#pragma unroll
            for (int mt = 0; mt < 4; mt++)
#pragma unroll
                for (int nt = 0; nt < 8; nt++)
                    mma16816(acc[mt][nt], af[mt], &bf[nt >> 1][(nt & 1) * 2]);
        }
    }

    // register -> global epilogue
#pragma unroll
    for (int nt = 0; nt < 8; nt++) {
        const int col = n0 + wn * 64 + nt * 8 + qc * 2;
        const float2 bv = *(const float2*)(bias + col);
#pragma unroll
        for (int mt = 0; mt < 4; mt++) {
            const int row = m0 + wm * 64 + mt * 16 + qr;
            float a0 = acc[mt][nt][0] + bv.x, a1 = acc[mt][nt][1] + bv.y;
            float a2 = acc[mt][nt][2] + bv.x, a3 = acc[mt][nt][3] + bv.y;
            if (EPI == 1) {
                a0 = fmaxf(a0, 0.f); a1 = fmaxf(a1, 0.f);
                a2 = fmaxf(a2, 0.f); a3 = fmaxf(a3, 0.f);
            }
            if (OUTH) {
                __half* C = (__half*)Cv;
                *(uint32_t*)(C + (size_t)row * N + col)       = f22u(a0, a1);
                *(uint32_t*)(C + (size_t)(row + 8) * N + col) = f22u(a2, a3);
            } else {
                float* C = (float*)Cv;
                *(float2*)(C + (size_t)row * N + col)       = make_float2(a0, a1);
                *(float2*)(C + (size_t)(row + 8) * N + col) = make_float2(a2, a3);
            }
        }
    }
}

// merged qkv + kv2 projection: grid.x = 5 (3 qkv tiles + 2 kv2 tiles of 256)
__global__ __launch_bounds__(256, 1)
void proj_kernel(const __half* __restrict__ x1h, const __half* __restrict__ x2h,
                 const __half* __restrict__ wqkvT, const float* __restrict__ bqkv,
                 __half* __restrict__ qkv, __half* __restrict__ kv2)
{
    extern __shared__ __half smh[];
    const int bx = blockIdx.x;
    const int m0 = blockIdx.y * BM;
    if (bx < 3)
        gemm_body<0, 1>(x1h, wqkvT, bqkv, qkv, smh, m0, bx * 256, 768, 256, threadIdx.x);
    else
        gemm_body<0, 1>(x2h, wqkvT + 256 * CD, bqkv + 256, kv2, smh,
                        m0, (bx - 3) * 256, 512, 256, threadIdx.x);
}

template <int EPI, int OUTH>
__global__ __launch_bounds__(256, 1)
void gemm_h(const __half* __restrict__ A, const __half* __restrict__ WT,
            const float* __restrict__ bias, void* __restrict__ Cv, int N, int K)
{
    extern __shared__ __half smh[];
    gemm_body<EPI, OUTH>(A, WT, bias, Cv, smh,
                         blockIdx.y * BM, blockIdx.x * BN, N, K, threadIdx.x);
}

// ============================================================================
// FlashAttention-style dual-source graph attention (exact R7/R12 version).
// ============================================================================
#define KPADH 40
#define SM_K_H   (256 * KPADH)
#define SM_V_H   (256 * KPADH)
#define ATT_BM_OFF ((SM_K_H + SM_V_H) * 2)
#define ATT_SMEM_BYTES (ATT_BM_OFF + (1024 + 8) * 4)

__global__ __launch_bounds__(256, 2)
void attn_kernel(const __half* __restrict__ qkv, const __half* __restrict__ kv2,
                 const uint32_t* __restrict__ bm1, const uint32_t* __restrict__ bm2,
                 __half* __restrict__ ctx)
{
    extern __shared__ __half smh[];
    __half* sK = smh;
    __half* sV = sK + SM_K_H;
    uint32_t* sBM  = (uint32_t*)((char*)smh + ATT_BM_OFF);
    uint32_t* sBM2 = sBM + 1024;

    const int b  = blockIdx.z;
    const int h  = blockIdx.y;
    const int q0 = blockIdx.x * 128;
    const int tid  = threadIdx.x;
    const int warp = tid >> 5;
    const int lane = tid & 31;
    const int qr   = lane >> 2;
    const int qc   = lane & 3;
    const int arow = (lane & 7) + 8 * ((lane >> 3) & 1);
    const int acol = 8 * (lane >> 4);
    const int brow = (lane & 7) + 8 * (lane >> 4);
    const int bcol = 8 * ((lane >> 3) & 1);

#pragma unroll
    for (int j = 0; j < 4; j++) {
        int i = tid + j * 256;
        sBM[i] = bm1[((size_t)(b * CN1) + q0 + (i >> 3)) * 8 + (i & 7)];
    }
    if (tid < 8) sBM2[tid] = bm2[b * 8 + tid];

    uint32_t qf[2][4];
    {
        const __half* Qb = qkv + (size_t)(b * CN1 + q0 + warp * 16) * 768 + h * CDH;
#pragma unroll
        for (int kc = 0; kc < 2; kc++) {
            const __half* p = Qb + kc * 16 + 2 * qc;
            qf[kc][0] = *(const uint32_t*)(p + (size_t)qr * 768);
            qf[kc][1] = *(const uint32_t*)(p + (size_t)(qr + 8) * 768);
            qf[kc][2] = *(const uint32_t*)(p + (size_t)qr * 768 + 8);
            qf[kc][3] = *(const uint32_t*)(p + (size_t)(qr + 8) * 768 + 8);
        }
    }

    float ofin[4][4];
#pragma unroll
    for (int n = 0; n < 4; n++)
#pragma unroll
        for (int e = 0; e < 4; e++) ofin[n][e] = 0.0f;

#pragma unroll 1
    for (int src = 0; src < 2; src++) {
        const __half* base = src ? kv2 : qkv;
        const int stride  = src ? 512 : 768;
        const int koff    = src ? 0   : 256;
        const int voff    = src ? 256 : 512;

        __syncthreads();
#pragma unroll
        for (int j = 0; j < 4; j++) {
            int i = tid + j * 256;
            int r = i >> 2, c8 = (i & 3) * 8;
            const __half* row = base + (size_t)(b * 256 + r) * stride + h * CDH;
            *(uint4*)(sK + r * KPADH + c8) = *(const uint4*)(row + koff + c8);
            *(uint4*)(sV + r * KPADH + c8) = *(const uint4*)(row + voff + c8);
        }
        __syncthreads();

        float m0 = -1e30f, m1 = -1e30f, l0 = 0.0f, l1 = 0.0f;
        float o[4][4];
#pragma unroll
        for (int n = 0; n < 4; n++)
#pragma unroll
            for (int e = 0; e < 4; e++) o[n][e] = 0.0f;

#pragma unroll 1
        for (int chunk = 0; chunk < 4; chunk++) {
            const int key0 = chunk * 64;

            float s[8][4];
#pragma unroll
            for (int nf = 0; nf < 8; nf++)
                s[nf][0] = s[nf][1] = s[nf][2] = s[nf][3] = 0.0f;
#pragma unroll
            for (int pr = 0; pr < 4; pr++) {
                const __half* kbase = sK + (size_t)(key0 + pr * 16 + brow) * KPADH + bcol;
                uint32_t kb0[4], kb1[4];
                ldsm4(kb0, kbase);
                ldsm4(kb1, kbase + 16);
                mma16816(s[2 * pr],     qf[0], kb0 + 0);
                mma16816(s[2 * pr],     qf[1], kb1 + 0);
                mma16816(s[2 * pr + 1], qf[0], kb0 + 2);
                mma16816(s[2 * pr + 1], qf[1], kb1 + 2);
            }

            uint32_t wa0, wa1, wb0, wb1;
            if (src == 0) {
                const uint32_t* ra = sBM + (warp * 16 + qr) * 8 + chunk * 2;
                const uint32_t* rb = sBM + (warp * 16 + qr + 8) * 8 + chunk * 2;
                wa0 = ra[0]; wa1 = ra[1]; wb0 = rb[0]; wb1 = rb[1];
            } else {
                wa0 = sBM2[chunk * 2]; wa1 = sBM2[chunk * 2 + 1];
                wb0 = wa0; wb1 = wa1;
            }
            float cm0 = -1e30f, cm1 = -1e30f;
#pragma unroll
            for (int nf = 0; nf < 8; nf++) {
                const int sh = (nf & 3) * 8 + qc * 2;
                const uint32_t ba = ((nf < 4 ? wa0 : wa1) >> sh);
                const uint32_t bb = ((nf < 4 ? wb0 : wb1) >> sh);
                s[nf][0] = (ba & 1u) ? s[nf][0] : -1e9f;
                s[nf][1] = (ba & 2u) ? s[nf][1] : -1e9f;
                s[nf][2] = (bb & 1u) ? s[nf][2] : -1e9f;
                s[nf][3] = (bb & 2u) ? s[nf][3] : -1e9f;
                cm0 = fmaxf(cm0, fmaxf(s[nf][0], s[nf][1]));
                cm1 = fmaxf(cm1, fmaxf(s[nf][2], s[nf][3]));
            }
            cm0 = fmaxf(cm0, __shfl_xor_sync(0xffffffffu, cm0, 1));
            cm0 = fmaxf(cm0, __shfl_xor_sync(0xffffffffu, cm0, 2));
            cm1 = fmaxf(cm1, __shfl_xor_sync(0xffffffffu, cm1, 1));
            cm1 = fmaxf(cm1, __shfl_xor_sync(0xffffffffu, cm1, 2));

            const float mn0 = fmaxf(m0, cm0), mn1 = fmaxf(m1, cm1);
            const float f0 = ex2f(m0 - mn0), f1 = ex2f(m1 - mn1);
            m0 = mn0; m1 = mn1;
            l0 *= f0; l1 *= f1;
#pragma unroll
            for (int n = 0; n < 4; n++) {
                o[n][0] *= f0; o[n][1] *= f0;
                o[n][2] *= f1; o[n][3] *= f1;
            }

#pragma unroll
            for (int nf = 0; nf < 8; nf++) {
                s[nf][0] = ex2f(s[nf][0] - mn0);
                s[nf][1] = ex2f(s[nf][1] - mn0);
                s[nf][2] = ex2f(s[nf][2] - mn1);
                s[nf][3] = ex2f(s[nf][3] - mn1);
                l0 += s[nf][0] + s[nf][1];
                l1 += s[nf][2] + s[nf][3];
            }

#pragma unroll
            for (int j = 0; j < 4; j++) {
                uint32_t ap[4];
                ap[0] = f22u(s[2*j][0],   s[2*j][1]);
                ap[1] = f22u(s[2*j][2],   s[2*j][3]);
                ap[2] = f22u(s[2*j+1][0], s[2*j+1][1]);
                ap[3] = f22u(s[2*j+1][2], s[2*j+1][3]);
                const __half* vbase = sV + (size_t)(key0 + j * 16 + arow) * KPADH + acol;
                uint32_t vb0[4], vb1[4];
                ldsm4t(vb0, vbase);
                ldsm4t(vb1, vbase + 16);
                mma16816(o[0], ap, vb0 + 0);
                mma16816(o[1], ap, vb0 + 2);
                mma16816(o[2], ap, vb1 + 0);
                mma16816(o[3], ap, vb1 + 2);
            }
        }

        l0 += __shfl_xor_sync(0xffffffffu, l0, 1);
        l0 += __shfl_xor_sync(0xffffffffu, l0, 2);
        l1 += __shfl_xor_sync(0xffffffffu, l1, 1);
        l1 += __shfl_xor_sync(0xffffffffu, l1, 2);
        const float i0 = 1.0f / l0, i1 = 1.0f / l1;
#pragma unroll
        for (int n = 0; n < 4; n++) {
            ofin[n][0] += o[n][0] * i0;
            ofin[n][1] += o[n][1] * i0;
            ofin[n][2] += o[n][2] * i1;
            ofin[n][3] += o[n][3] * i1;
        }
    }

    __half* outA = ctx + (size_t)(b * CN1 + q0 + warp * 16 + qr) * CD + h * CDH + qc * 2;
    __half* outB = outA + 8 * CD;
#pragma unroll
    for (int n = 0; n < 4; n++) {
        *(uint32_t*)(outA + n * 8) = f22u(ofin[n][0], ofin[n][1]);
        *(uint32_t*)(outB + n * 8) = f22u(ofin[n][2], ofin[n][3]);
    }
}

// ============================================================================
// out = LayerNorm(X + Y) * g + be   (exact R7/R12 version)
// ============================================================================
template <int WH>
__global__ __launch_bounds__(256)
void add_ln_kernel(const float* __restrict__ X, const float* __restrict__ Y,
                   const float* __restrict__ g, const float* __restrict__ be,
                   float* __restrict__ outF, __half* __restrict__ outH)
{
    const int warp = threadIdx.x >> 5;
    const int lane = threadIdx.x & 31;
    const size_t row = (size_t)blockIdx.x * 8 + warp;
    const float* x = X + row * CD;
    const float* y = Y + row * CD;
    float v[8];
    float s = 0.0f;
#pragma unroll
    for (int i = 0; i < 8; i++) { v[i] = x[lane + i * 32] + y[lane + i * 32]; s += v[i]; }
#pragma unroll
    for (int o = 16; o > 0; o >>= 1) s += __shfl_xor_sync(0xffffffffu, s, o);
    const float mu = s * (1.0f / CD);
    float s2 = 0.0f;
#pragma unroll
    for (int i = 0; i < 8; i++) { float d = v[i] - mu; s2 += d * d; }
#pragma unroll
    for (int o = 16; o > 0; o >>= 1) s2 += __shfl_xor_sync(0xffffffffu, s2, o);
    const float inv = rsqrtf(s2 * (1.0f / CD) + 1e-6f);
#pragma unroll
    for (int i = 0; i < 8; i++) {
        int c = lane + i * 32;
        float r = g[c] * (v[i] - mu) * inv + be[c];
        outF[row * CD + c] = r;
        if (WH) outH[row * CD + c] = __float2half(r);
    }
}

// ============================================================================
// packing kernels (exact R7/R12 versions)
// ============================================================================
__global__ void pack_weights(const float* __restrict__ Wq, const float* __restrict__ Wk,
                             const float* __restrict__ Wv, const float* __restrict__ Wo,
                             const float* __restrict__ W1, const float* __restrict__ W2,
                             __half* __restrict__ wqkvT, __half* __restrict__ woT,
                             __half* __restrict__ w1T,  __half* __restrict__ w2T)
{
    __shared__ float tile[32][33];
    const int z = blockIdx.z;
    const float* src; __half* dst; int K, N; float scale = 1.0f;
    switch (z) {
        case 0: src = Wq; dst = wqkvT;            K = CD;   N = CD;   scale = QSCALE; break;
        case 1: src = Wk; dst = wqkvT + 256 * CD; K = CD;   N = CD;   break;
        case 2: src = Wv; dst = wqkvT + 512 * CD; K = CD;   N = CD;   break;
        case 3: src = Wo; dst = woT;              K = CD;   N = CD;   break;
        case 4: src = W1; dst = w1T;              K = CD;   N = CDFF; break;
        default: src = W2; dst = w2T;             K = CDFF; N = CD;   break;
    }
    const int k0 = blockIdx.y * 32, n0 = blockIdx.x * 32;
    if (k0 >= K || n0 >= N) return;
    const int tx = threadIdx.x, ty = threadIdx.y;
#pragma unroll
    for (int i = 0; i < 32; i += 8) tile[ty + i][tx] = src[(size_t)(k0 + ty + i) * N + n0 + tx];
    __syncthreads();
#pragma unroll
    for (int i = 0; i < 32; i += 8)
        dst[(size_t)(n0 + ty + i) * K + k0 + tx] = __float2half(tile[tx][ty + i] * scale);
}

__global__ void pack_misc(const float* __restrict__ x1, const float* __restrict__ x2,
                          const float* __restrict__ bq, const float* __restrict__ bk,
                          const float* __restrict__ bv,
                          __half* __restrict__ x1h, __half* __restrict__ x2h,
                          float* __restrict__ bqkv)
{
    const size_t i = (size_t)blockIdx.x * 256 + threadIdx.x;
    x1h[i] = __float2half(x1[i]);
    x2h[i] = __float2half(x2[i]);
    if (i < 256) {
        bqkv[i]       = bq[i] * QSCALE;
        bqkv[256 + i] = bk[i];
        bqkv[512 + i] = bv[i];
    }
}

__global__ void build_bm(const float* __restrict__ adj, const float* __restrict__ mask1,
                         const float* __restrict__ mask2,
                         uint32_t* __restrict__ bm1, uint32_t* __restrict__ bm2)
{
    const int lane = threadIdx.x & 31;
    if (blockIdx.x < 4096) {
        const int gw = (blockIdx.x * 256 + threadIdx.x) >> 5;
        const int b = gw >> 8;
        const float* arow = adj + (size_t)gw * 256;
        const float* m1 = mask1 + (size_t)b * 256;
#pragma unroll
        for (int w = 0; w < 8; w++) {
            float v = arow[w * 32 + lane] * m1[w * 32 + lane];
            uint32_t bits = __ballot_sync(0xffffffffu, v > 0.0f);
            if (lane == 0) bm1[(size_t)gw * 8 + w] = bits;
        }
    } else {
        const int b = blockIdx.x - 4096;
        const int w = threadIdx.x >> 5;
        float v = mask2[(size_t)b * 256 + w * 32 + lane];
        uint32_t bits = __ballot_sync(0xffffffffu, v > 0.0f);
        if (lane == 0) bm2[b * 8 + w] = bits;
    }
}

// ============================================================================
// Host launch
// ============================================================================
extern "C" void kernel_launch(void* const* d_in, const int* in_sizes, int n_in,
                              void* d_out, int out_size)
{
    const float* x1    = (const float*)d_in[0];
    const float* adj1  = (const float*)d_in[1];
    const float* mask1 = (const float*)d_in[2];
    const float* x2    = (const float*)d_in[3];
    const float* mask2 = (const float*)d_in[4];
    const float* Wq = (const float*)d_in[5];  const float* bq = (const float*)d_in[6];
    const float* Wk = (const float*)d_in[7];  const float* bk = (const float*)d_in[8];
    const float* Wv = (const float*)d_in[9];  const float* bv = (const float*)d_in[10];
    const float* Wo = (const float*)d_in[11]; const float* bo = (const float*)d_in[12];
    const float* W1 = (const float*)d_in[13]; const float* b1 = (const float*)d_in[14];
    const float* W2 = (const float*)d_in[15]; const float* b2 = (const float*)d_in[16];
    const float* g1 = (const float*)d_in[17]; const float* be1 = (const float*)d_in[18];
    const float* g2 = (const float*)d_in[19]; const float* be2 = (const float*)d_in[20];
    float* out = (float*)d_out;

    __half *wqkvT, *woT, *w1T, *w2T, *x1h, *x2h, *qkv, *kv2, *ctx, *o1h, *hid;
    float *bqkv, *tmp, *o1f;
    uint32_t *bm1, *bm2;
    cudaGetSymbolAddress((void**)&wqkvT, g_wqkvT);
    cudaGetSymbolAddress((void**)&woT,   g_woT);
    cudaGetSymbolAddress((void**)&w1T,   g_w1T);
    cudaGetSymbolAddress((void**)&w2T,   g_w2T);
    cudaGetSymbolAddress((void**)&bqkv,  g_bqkv);
    cudaGetSymbolAddress((void**)&x1h,   g_x1h);
    cudaGetSymbolAddress((void**)&x2h,   g_x2h);
    cudaGetSymbolAddress((void**)&qkv,   g_qkv);
    cudaGetSymbolAddress((void**)&kv2,   g_kv2);
    cudaGetSymbolAddress((void**)&ctx,   g_ctx);
    cudaGetSymbolAddress((void**)&tmp,   g_tmp);
    cudaGetSymbolAddress((void**)&o1f,   g_o1f);
    cudaGetSymbolAddress((void**)&o1h,   g_o1h);
    cudaGetSymbolAddress((void**)&hid,   g_hid);
    cudaGetSymbolAddress((void**)&bm1,   g_bm1);
    cudaGetSymbolAddress((void**)&bm2,   g_bm2);

    cudaFuncSetAttribute(proj_kernel, cudaFuncAttributeMaxDynamicSharedMemorySize, GSMEM_BYTES);
    cudaFuncSetAttribute(gemm_h<0,0>, cudaFuncAttributeMaxDynamicSharedMemorySize, GSMEM_BYTES);
    cudaFuncSetAttribute(gemm_h<1,1>, cudaFuncAttributeMaxDynamicSharedMemorySize, GSMEM_BYTES);
    cudaFuncSetAttribute(attn_kernel, cudaFuncAttributeMaxDynamicSharedMemorySize, ATT_SMEM_BYTES);

    const int M = CB * CN1;

    pack_weights<<<dim3(32, 32, 6), dim3(32, 8)>>>(Wq, Wk, Wv, Wo, W1, W2,
                                                   wqkvT, woT, w1T, w2T);
    pack_misc<<<M * CD / 256, 256>>>(x1, x2, bq, bk, bv, x1h, x2h, bqkv);
    build_bm<<<4096 + CB, 256>>>(adj1, mask1, mask2, bm1, bm2);

    // merged qkv + kv2 projection (1280 CTAs of 128x256)
    proj_kernel<<<dim3(5, M / BM), 256, GSMEM_BYTES>>>(x1h, x2h, wqkvT, bqkv, qkv, kv2);

    attn_kernel<<<dim3(CN1 / 128, CH, CB), 256, ATT_SMEM_BYTES>>>(qkv, kv2, bm1, bm2, ctx);

    gemm_h<0,0><<<dim3(1, M / BM), 256, GSMEM_BYTES>>>(ctx, woT, bo, tmp, CD, CD);
    add_ln_kernel<1><<<M / 8, 256>>>(x1, tmp, g1, be1, o1f, o1h);

    gemm_h<1,1><<<dim3(4, M / BM), 256, GSMEM_BYTES>>>(o1h, w1T, b1, hid, CDFF, CD);
    gemm_h<0,0><<<dim3(1, M / BM), 256, GSMEM_BYTES>>>(hid, w2T, b2, tmp, CD, CDFF);
    add_ln_kernel<0><<<M / 8, 256>>>(o1f, tmp, g2, be2, out, nullptr);
}

// round 14
// speedup vs baseline: 1.1053x; 1.1053x over previous
#include <cuda_runtime.h>
#include <cuda_fp16.h>
#include <cstdint>

#define CB   128
#define CN1  256
#define CN2  256
#define CD   256
#define CH   8
#define CDH  32
#define CDFF 1024

// ---------------- scratch (device globals) ----------------
__device__ __half g_wqkvT[768 * CD];      // [N][K] half, q-part pre-scaled
__device__ __half g_woT  [CD * CD];
__device__ __half g_w1T  [CDFF * CD];
__device__ __half g_w2T  [CD * CDFF];
__device__ float  g_bqkv [768];
__device__ __half g_x1h  [CB * CN1 * CD];
__device__ __half g_x2h  [CB * CN2 * CD];
__device__ __half g_qkv  [CB * CN1 * 768];
__device__ __half g_kv2  [CB * CN2 * 512];
__device__ __half g_ctx  [CB * CN1 * CD];
__device__ float  g_tmp  [CB * CN1 * CD];
__device__ float  g_o1f  [CB * CN1 * CD];
__device__ __half g_o1h  [CB * CN1 * CD];
__device__ __half g_hid  [CB * CN1 * CDFF];
__device__ uint32_t g_bm1[CB * CN1 * 8];
__device__ uint32_t g_bm2[CB * 8];

#define QSCALE (0.17677669529663687f * 1.4426950408889634f)

// ---------------- helpers ----------------
__device__ __forceinline__ void cp16(void* s, const void* g) {
    unsigned sa = (unsigned)__cvta_generic_to_shared(s);
    asm volatile("cp.async.cg.shared.global [%0], [%1], 16;\n" :: "r"(sa), "l"(g));
}
__device__ __forceinline__ void cp_commit() { asm volatile("cp.async.commit_group;\n"); }
template <int N> __device__ __forceinline__ void cp_wait() {
    asm volatile("cp.async.wait_group %0;\n" :: "n"(N));
}
__device__ __forceinline__ void mma16816(float* d, const uint32_t* a, const uint32_t* b) {
    asm volatile(
        "mma.sync.aligned.m16n8k16.row.col.f32.f16.f16.f32 "
        "{%0,%1,%2,%3}, {%4,%5,%6,%7}, {%8,%9}, {%0,%1,%2,%3};"
        : "+f"(d[0]), "+f"(d[1]), "+f"(d[2]), "+f"(d[3])
        : "r"(a[0]), "r"(a[1]), "r"(a[2]), "r"(a[3]), "r"(b[0]), "r"(b[1]));
}
__device__ __forceinline__ void ldsm4(uint32_t* r, const __half* p) {
    uint32_t a = (uint32_t)__cvta_generic_to_shared(p);
    asm volatile("ldmatrix.sync.aligned.m8n8.x4.shared.b16 {%0,%1,%2,%3}, [%4];"
                 : "=r"(r[0]), "=r"(r[1]), "=r"(r[2]), "=r"(r[3]) : "r"(a));
}
__device__ __forceinline__ void ldsm4t(uint32_t* r, const __half* p) {
    uint32_t a = (uint32_t)__cvta_generic_to_shared(p);
    asm volatile("ldmatrix.sync.aligned.m8n8.x4.trans.shared.b16 {%0,%1,%2,%3}, [%4];"
                 : "=r"(r[0]), "=r"(r[1]), "=r"(r[2]), "=r"(r[3]) : "r"(a));
}
__device__ __forceinline__ float ex2f(float x) {
    float y; asm("ex2.approx.f32 %0, %1;" : "=f"(y) : "f"(x)); return y;
}
__device__ __forceinline__ uint32_t f22u(float a, float b) {
    __half2 h = __floats2half2_rn(a, b);
    return *(uint32_t*)&h;
}

// ============================================================================
// fp16 GEMM body: block 128x128x64, 4 warps, warp 64x64 (per-warp sequence
// identical to R7/R12), m16n8k16, ldmatrix, 3-stage cp.async (depth-2
// prefetch), runtime N/K. Half the pipeline turns of the BK=32 version.
// ============================================================================
#define BM 128
#define BN 128
#define BK 64
#define APADH 72                                  // 64 + 8 pad (conflict-free)
#define STGH (2 * 128 * APADH)                    // A + B rows per stage
#define GS 3
#define GSMEM_BYTES (GS * STGH * 2)               // 110592

template <int EPI, int OUTH>
__device__ __forceinline__ void gemm_body(
    const __half* __restrict__ A, const __half* __restrict__ WT,
    const float* __restrict__ bias, void* __restrict__ Cv,
    __half* smh, int m0, int n0, int N, int K, int tid)
{
    const int warp = tid >> 5;
    const int lane = tid & 31;
    const int wm   = warp & 1;
    const int wn   = warp >> 1;
    const int kt   = K / BK;                      // >= 4 for all our GEMMs
    const int qr   = lane >> 2;
    const int qc   = lane & 3;
    const int arow = (lane & 7) + 8 * ((lane >> 3) & 1);
    const int acol = 8 * (lane >> 4);
    const int brow = (lane & 7) + 8 * (lane >> 4);
    const int bcol = 8 * ((lane >> 3) & 1);

    auto stageSlot = [&](int t) -> __half* {
        int s = t % GS;
        return smh + s * STGH;
    };

    auto loadStage = [&](int t) {
        __half* As = stageSlot(t);
        __half* Bs = As + 128 * APADH;
        const int k0 = t * BK;
#pragma unroll
        for (int j = 0; j < 8; j++) {             // 1024 16B chunks of A
            int i = tid + j * 128;
            int r = i >> 3, c8 = (i & 7) * 8;
            cp16(As + r * APADH + c8, A + (size_t)(m0 + r) * K + k0 + c8);
        }
#pragma unroll
        for (int j = 0; j < 8; j++) {             // 1024 16B chunks of B
            int i = tid + j * 128;
            int r = i >> 3, c8 = (i & 7) * 8;
            cp16(Bs + r * APADH + c8, WT + (size_t)(n0 + r) * K + k0 + c8);
        }
        cp_commit();
    };

    float acc[4][8][4];
#pragma unroll
    for (int mt = 0; mt < 4; mt++)
#pragma unroll
        for (int nt = 0; nt < 8; nt++)
#pragma unroll
            for (int e = 0; e < 4; e++) acc[mt][nt][e] = 0.0f;

    loadStage(0);
    loadStage(1);

    for (int t = 0; t < kt; t++) {
        if (t + 1 < kt) cp_wait<1>(); else cp_wait<0>();
        __syncthreads();
        if (t + 2 < kt) loadStage(t + 2);        // writes slot (t+2)%3: safe

        const __half* As = stageSlot(t) + (wm * 64) * APADH;
        const __half* Bs = stageSlot(t) + 128 * APADH + (wn * 64) * APADH;
#pragma unroll
        for (int kk = 0; kk < BK; kk += 16) {
            uint32_t af[4][4];
            uint32_t bf[4][4];
#pragma unroll
            for (int mt = 0; mt < 4; mt++)
                ldsm4(af[mt], As + (mt * 16 + arow) * APADH + kk + acol);
#pragma unroll
            for (int p = 0; p < 4; p++)
                ldsm4(bf[p], Bs + (p * 16 + brow) * APADH + kk + bcol);
#pragma unroll
            for (int mt = 0; mt < 4; mt++)
#pragma unroll
                for (int nt = 0; nt < 8; nt++)
                    mma16816(acc[mt][nt], af[mt], &bf[nt >> 1][(nt & 1) * 2]);
        }
    }

    // register -> global epilogue
#pragma unroll
    for (int nt = 0; nt < 8; nt++) {
        const int col = n0 + wn * 64 + nt * 8 + qc * 2;
        const float2 bv = *(const float2*)(bias + col);
#pragma unroll
        for (int mt = 0; mt < 4; mt++) {
            const int row = m0 + wm * 64 + mt * 16 + qr;
            float a0 = acc[mt][nt][0] + bv.x, a1 = acc[mt][nt][1] + bv.y;
            float a2 = acc[mt][nt][2] + bv.x, a3 = acc[mt][nt][3] + bv.y;
            if (EPI == 1) {
                a0 = fmaxf(a0, 0.f); a1 = fmaxf(a1, 0.f);
                a2 = fmaxf(a2, 0.f); a3 = fmaxf(a3, 0.f);
            }
            if (OUTH) {
                __half* C = (__half*)Cv;
                *(uint32_t*)(C + (size_t)row * N + col)       = f22u(a0, a1);
                *(uint32_t*)(C + (size_t)(row + 8) * N + col) = f22u(a2, a3);
            } else {
                float* C = (float*)Cv;
                *(float2*)(C + (size_t)row * N + col)       = make_float2(a0, a1);
                *(float2*)(C + (size_t)(row + 8) * N + col) = make_float2(a2, a3);
            }
        }
    }
}

// merged qkv + kv2 projection: grid.x = 10 (6 qkv tiles + 4 kv2 tiles)
__global__ __launch_bounds__(128, 2)
void proj_kernel(const __half* __restrict__ x1h, const __half* __restrict__ x2h,
                 const __half* __restrict__ wqkvT, const float* __restrict__ bqkv,
                 __half* __restrict__ qkv, __half* __restrict__ kv2)
{
    extern __shared__ __half smh[];
    const int bx = blockIdx.x;
    const int m0 = blockIdx.y * BM;
    if (bx < 6)
        gemm_body<0, 1>(x1h, wqkvT, bqkv, qkv, smh, m0, bx * 128, 768, 256, threadIdx.x);
    else
        gemm_body<0, 1>(x2h, wqkvT + 256 * CD, bqkv + 256, kv2, smh,
                        m0, (bx - 6) * 128, 512, 256, threadIdx.x);
}

template <int EPI, int OUTH>
__global__ __launch_bounds__(128, 2)
void gemm_h(const __half* __restrict__ A, const __half* __restrict__ WT,
            const float* __restrict__ bias, void* __restrict__ Cv, int N, int K)
{
    extern __shared__ __half smh[];
    gemm_body<EPI, OUTH>(A, WT, bias, Cv, smh,
                         blockIdx.y * BM, blockIdx.x * BN, N, K, threadIdx.x);
}

// ============================================================================
// FlashAttention-style dual-source graph attention (exact R7/R12 version).
// ============================================================================
#define KPADH 40
#define SM_K_H   (256 * KPADH)
#define SM_V_H   (256 * KPADH)
#define ATT_BM_OFF ((SM_K_H + SM_V_H) * 2)
#define ATT_SMEM_BYTES (ATT_BM_OFF + (1024 + 8) * 4)

__global__ __launch_bounds__(256, 2)
void attn_kernel(const __half* __restrict__ qkv, const __half* __restrict__ kv2,
                 const uint32_t* __restrict__ bm1, const uint32_t* __restrict__ bm2,
                 __half* __restrict__ ctx)
{
    extern __shared__ __half smh[];
    __half* sK = smh;
    __half* sV = sK + SM_K_H;
    uint32_t* sBM  = (uint32_t*)((char*)smh + ATT_BM_OFF);
    uint32_t* sBM2 = sBM + 1024;

    const int b  = blockIdx.z;
    const int h  = blockIdx.y;
    const int q0 = blockIdx.x * 128;
    const int tid  = threadIdx.x;
    const int warp = tid >> 5;
    const int lane = tid & 31;
    const int qr   = lane >> 2;
    const int qc   = lane & 3;
    const int arow = (lane & 7) + 8 * ((lane >> 3) & 1);
    const int acol = 8 * (lane >> 4);
    const int brow = (lane & 7) + 8 * (lane >> 4);
    const int bcol = 8 * ((lane >> 3) & 1);

#pragma unroll
    for (int j = 0; j < 4; j++) {
        int i = tid + j * 256;
        sBM[i] = bm1[((size_t)(b * CN1) + q0 + (i >> 3)) * 8 + (i & 7)];
    }
    if (tid < 8) sBM2[tid] = bm2[b * 8 + tid];

    uint32_t qf[2][4];
    {
        const __half* Qb = qkv + (size_t)(b * CN1 + q0 + warp * 16) * 768 + h * CDH;
#pragma unroll
        for (int kc = 0; kc < 2; kc++) {
            const __half* p = Qb + kc * 16 + 2 * qc;
            qf[kc][0] = *(const uint32_t*)(p + (size_t)qr * 768);
            qf[kc][1] = *(const uint32_t*)(p + (size_t)(qr + 8) * 768);
            qf[kc][2] = *(const uint32_t*)(p + (size_t)qr * 768 + 8);
            qf[kc][3] = *(const uint32_t*)(p + (size_t)(qr + 8) * 768 + 8);
        }
    }

    float ofin[4][4];
#pragma unroll
    for (int n = 0; n < 4; n++)
#pragma unroll
        for (int e = 0; e < 4; e++) ofin[n][e] = 0.0f;

#pragma unroll 1
    for (int src = 0; src < 2; src++) {
        const __half* base = src ? kv2 : qkv;
        const int stride  = src ? 512 : 768;
        const int koff    = src ? 0   : 256;
        const int voff    = src ? 256 : 512;

        __syncthreads();
#pragma unroll
        for (int j = 0; j < 4; j++) {
            int i = tid + j * 256;
            int r = i >> 2, c8 = (i & 3) * 8;
            const __half* row = base + (size_t)(b * 256 + r) * stride + h * CDH;
            *(uint4*)(sK + r * KPADH + c8) = *(const uint4*)(row + koff + c8);
            *(uint4*)(sV + r * KPADH + c8) = *(const uint4*)(row + voff + c8);
        }
        __syncthreads();

        float m0 = -1e30f, m1 = -1e30f, l0 = 0.0f, l1 = 0.0f;
        float o[4][4];
#pragma unroll
        for (int n = 0; n < 4; n++)
#pragma unroll
            for (int e = 0; e < 4; e++) o[n][e] = 0.0f;

#pragma unroll 1
        for (int chunk = 0; chunk < 4; chunk++) {
            const int key0 = chunk * 64;

            float s[8][4];
#pragma unroll
            for (int nf = 0; nf < 8; nf++)
                s[nf][0] = s[nf][1] = s[nf][2] = s[nf][3] = 0.0f;
#pragma unroll
            for (int pr = 0; pr < 4; pr++) {
                const __half* kbase = sK + (size_t)(key0 + pr * 16 + brow) * KPADH + bcol;
                uint32_t kb0[4], kb1[4];
                ldsm4(kb0, kbase);
                ldsm4(kb1, kbase + 16);
                mma16816(s[2 * pr],     qf[0], kb0 + 0);
                mma16816(s[2 * pr],     qf[1], kb1 + 0);
                mma16816(s[2 * pr + 1], qf[0], kb0 + 2);
                mma16816(s[2 * pr + 1], qf[1], kb1 + 2);
            }

            uint32_t wa0, wa1, wb0, wb1;
            if (src == 0) {
                const uint32_t* ra = sBM + (warp * 16 + qr) * 8 + chunk * 2;
                const uint32_t* rb = sBM + (warp * 16 + qr + 8) * 8 + chunk * 2;
                wa0 = ra[0]; wa1 = ra[1]; wb0 = rb[0]; wb1 = rb[1];
            } else {
                wa0 = sBM2[chunk * 2]; wa1 = sBM2[chunk * 2 + 1];
                wb0 = wa0; wb1 = wa1;
            }
            float cm0 = -1e30f, cm1 = -1e30f;
#pragma unroll
            for (int nf = 0; nf < 8; nf++) {
                const int sh = (nf & 3) * 8 + qc * 2;
                const uint32_t ba = ((nf < 4 ? wa0 : wa1) >> sh);
                const uint32_t bb = ((nf < 4 ? wb0 : wb1) >> sh);
                s[nf][0] = (ba & 1u) ? s[nf][0] : -1e9f;
                s[nf][1] = (ba & 2u) ? s[nf][1] : -1e9f;
                s[nf][2] = (bb & 1u) ? s[nf][2] : -1e9f;
                s[nf][3] = (bb & 2u) ? s[nf][3] : -1e9f;
                cm0 = fmaxf(cm0, fmaxf(s[nf][0], s[nf][1]));
                cm1 = fmaxf(cm1, fmaxf(s[nf][2], s[nf][3]));
            }
            cm0 = fmaxf(cm0, __shfl_xor_sync(0xffffffffu, cm0, 1));
            cm0 = fmaxf(cm0, __shfl_xor_sync(0xffffffffu, cm0, 2));
            cm1 = fmaxf(cm1, __shfl_xor_sync(0xffffffffu, cm1, 1));
            cm1 = fmaxf(cm1, __shfl_xor_sync(0xffffffffu, cm1, 2));

            const float mn0 = fmaxf(m0, cm0), mn1 = fmaxf(m1, cm1);
            const float f0 = ex2f(m0 - mn0), f1 = ex2f(m1 - mn1);
            m0 = mn0; m1 = mn1;
            l0 *= f0; l1 *= f1;
#pragma unroll
            for (int n = 0; n < 4; n++) {
                o[n][0] *= f0; o[n][1] *= f0;
                o[n][2] *= f1; o[n][3] *= f1;
            }

#pragma unroll
            for (int nf = 0; nf < 8; nf++) {
                s[nf][0] = ex2f(s[nf][0] - mn0);
                s[nf][1] = ex2f(s[nf][1] - mn0);
                s[nf][2] = ex2f(s[nf][2] - mn1);
                s[nf][3] = ex2f(s[nf][3] - mn1);
                l0 += s[nf][0] + s[nf][1];
                l1 += s[nf][2] + s[nf][3];
            }

#pragma unroll
            for (int j = 0; j < 4; j++) {
                uint32_t ap[4];
                ap[0] = f22u(s[2*j][0],   s[2*j][1]);
                ap[1] = f22u(s[2*j][2],   s[2*j][3]);
                ap[2] = f22u(s[2*j+1][0], s[2*j+1][1]);
                ap[3] = f22u(s[2*j+1][2], s[2*j+1][3]);
                const __half* vbase = sV + (size_t)(key0 + j * 16 + arow) * KPADH + acol;
                uint32_t vb0[4], vb1[4];
                ldsm4t(vb0, vbase);
                ldsm4t(vb1, vbase + 16);
                mma16816(o[0], ap, vb0 + 0);
                mma16816(o[1], ap, vb0 + 2);
                mma16816(o[2], ap, vb1 + 0);
                mma16816(o[3], ap, vb1 + 2);
            }
        }

        l0 += __shfl_xor_sync(0xffffffffu, l0, 1);
        l0 += __shfl_xor_sync(0xffffffffu, l0, 2);
        l1 += __shfl_xor_sync(0xffffffffu, l1, 1);
        l1 += __shfl_xor_sync(0xffffffffu, l1, 2);
        const float i0 = 1.0f / l0, i1 = 1.0f / l1;
#pragma unroll
        for (int n = 0; n < 4; n++) {
            ofin[n][0] += o[n][0] * i0;
            ofin[n][1] += o[n][1] * i0;
            ofin[n][2] += o[n][2] * i1;
            ofin[n][3] += o[n][3] * i1;
        }
    }

    __half* outA = ctx + (size_t)(b * CN1 + q0 + warp * 16 + qr) * CD + h * CDH + qc * 2;
    __half* outB = outA + 8 * CD;
#pragma unroll
    for (int n = 0; n < 4; n++) {
        *(uint32_t*)(outA + n * 8) = f22u(ofin[n][0], ofin[n][1]);
        *(uint32_t*)(outB + n * 8) = f22u(ofin[n][2], ofin[n][3]);
    }
}

// ============================================================================
// out = LayerNorm(X + Y) * g + be   (exact R7/R12 version)
// ============================================================================
template <int WH>
__global__ __launch_bounds__(256)
void add_ln_kernel(const float* __restrict__ X, const float* __restrict__ Y,
                   const float* __restrict__ g, const float* __restrict__ be,
                   float* __restrict__ outF, __half* __restrict__ outH)
{
    const int warp = threadIdx.x >> 5;
    const int lane = threadIdx.x & 31;
    const size_t row = (size_t)blockIdx.x * 8 + warp;
    const float* x = X + row * CD;
    const float* y = Y + row * CD;
    float v[8];
    float s = 0.0f;
#pragma unroll
    for (int i = 0; i < 8; i++) { v[i] = x[lane + i * 32] + y[lane + i * 32]; s += v[i]; }
#pragma unroll
    for (int o = 16; o > 0; o >>= 1) s += __shfl_xor_sync(0xffffffffu, s, o);
    const float mu = s * (1.0f / CD);
    float s2 = 0.0f;
#pragma unroll
    for (int i = 0; i < 8; i++) { float d = v[i] - mu; s2 += d * d; }
#pragma unroll
    for (int o = 16; o > 0; o >>= 1) s2 += __shfl_xor_sync(0xffffffffu, s2, o);
    const float inv = rsqrtf(s2 * (1.0f / CD) + 1e-6f);
#pragma unroll
    for (int i = 0; i < 8; i++) {
        int c = lane + i * 32;
        float r = g[c] * (v[i] - mu) * inv + be[c];
        outF[row * CD + c] = r;
        if (WH) outH[row * CD + c] = __float2half(r);
    }
}

// ============================================================================
// packing kernels (exact R7/R12 versions)
// ============================================================================
__global__ void pack_weights(const float* __restrict__ Wq, const float* __restrict__ Wk,
                             const float* __restrict__ Wv, const float* __restrict__ Wo,
                             const float* __restrict__ W1, const float* __restrict__ W2,
                             __half* __restrict__ wqkvT, __half* __restrict__ woT,
                             __half* __restrict__ w1T,  __half* __restrict__ w2T)
{
    __shared__ float tile[32][33];
    const int z = blockIdx.z;
    const float* src; __half* dst; int K, N; float scale = 1.0f;
    switch (z) {
        case 0: src = Wq; dst = wqkvT;            K = CD;   N = CD;   scale = QSCALE; break;
        case 1: src = Wk; dst = wqkvT + 256 * CD; K = CD;   N = CD;   break;
        case 2: src = Wv; dst = wqkvT + 512 * CD; K = CD;   N = CD;   break;
        case 3: src = Wo; dst = woT;              K = CD;   N = CD;   break;
        case 4: src = W1; dst = w1T;              K = CD;   N = CDFF; break;
        default: src = W2; dst = w2T;             K = CDFF; N = CD;   break;
    }
    const int k0 = blockIdx.y * 32, n0 = blockIdx.x * 32;
    if (k0 >= K || n0 >= N) return;
    const int tx = threadIdx.x, ty = threadIdx.y;
#pragma unroll
    for (int i = 0; i < 32; i += 8) tile[ty + i][tx] = src[(size_t)(k0 + ty + i) * N + n0 + tx];
    __syncthreads();
#pragma unroll
    for (int i = 0; i < 32; i += 8)
        dst[(size_t)(n0 + ty + i) * K + k0 + tx] = __float2half(tile[tx][ty + i] * scale);
}

__global__ void pack_misc(const float* __restrict__ x1, const float* __restrict__ x2,
                          const float* __restrict__ bq, const float* __restrict__ bk,
                          const float* __restrict__ bv,
                          __half* __restrict__ x1h, __half* __restrict__ x2h,
                          float* __restrict__ bqkv)
{
    const size_t i = (size_t)blockIdx.x * 256 + threadIdx.x;
    x1h[i] = __float2half(x1[i]);
    x2h[i] = __float2half(x2[i]);
    if (i < 256) {
        bqkv[i]       = bq[i] * QSCALE;
        bqkv[256 + i] = bk[i];
        bqkv[512 + i] = bv[i];
    }
}

__global__ void build_bm(const float* __restrict__ adj, const float* __restrict__ mask1,
                         const float* __restrict__ mask2,
                         uint32_t* __restrict__ bm1, uint32_t* __restrict__ bm2)
{
    const int lane = threadIdx.x & 31;
    if (blockIdx.x < 4096) {
        const int gw = (blockIdx.x * 256 + threadIdx.x) >> 5;
        const int b = gw >> 8;
        const float* arow = adj + (size_t)gw * 256;
        const float* m1 = mask1 + (size_t)b * 256;
#pragma unroll
        for (int w = 0; w < 8; w++) {
            float v = arow[w * 32 + lane] * m1[w * 32 + lane];
            uint32_t bits = __ballot_sync(0xffffffffu, v > 0.0f);
            if (lane == 0) bm1[(size_t)gw * 8 + w] = bits;
        }
    } else {
        const int b = blockIdx.x - 4096;
        const int w = threadIdx.x >> 5;
        float v = mask2[(size_t)b * 256 + w * 32 + lane];
        uint32_t bits = __ballot_sync(0xffffffffu, v > 0.0f);
        if (lane == 0) bm2[b * 8 + w] = bits;
    }
}

// ============================================================================
// Host launch
// ============================================================================
extern "C" void kernel_launch(void* const* d_in, const int* in_sizes, int n_in,
                              void* d_out, int out_size)
{
    const float* x1    = (const float*)d_in[0];
    const float* adj1  = (const float*)d_in[1];
    const float* mask1 = (const float*)d_in[2];
    const float* x2    = (const float*)d_in[3];
    const float* mask2 = (const float*)d_in[4];
    const float* Wq = (const float*)d_in[5];  const float* bq = (const float*)d_in[6];
    const float* Wk = (const float*)d_in[7];  const float* bk = (const float*)d_in[8];
    const float* Wv = (const float*)d_in[9];  const float* bv = (const float*)d_in[10];
    const float* Wo = (const float*)d_in[11]; const float* bo = (const float*)d_in[12];
    const float* W1 = (const float*)d_in[13]; const float* b1 = (const float*)d_in[14];
    const float* W2 = (const float*)d_in[15]; const float* b2 = (const float*)d_in[16];
    const float* g1 = (const float*)d_in[17]; const float* be1 = (const float*)d_in[18];
    const float* g2 = (const float*)d_in[19]; const float* be2 = (const float*)d_in[20];
    float* out = (float*)d_out;

    __half *wqkvT, *woT, *w1T, *w2T, *x1h, *x2h, *qkv, *kv2, *ctx, *o1h, *hid;
    float *bqkv, *tmp, *o1f;
    uint32_t *bm1, *bm2;
    cudaGetSymbolAddress((void**)&wqkvT, g_wqkvT);
    cudaGetSymbolAddress((void**)&woT,   g_woT);
    cudaGetSymbolAddress((void**)&w1T,   g_w1T);
    cudaGetSymbolAddress((void**)&w2T,   g_w2T);
    cudaGetSymbolAddress((void**)&bqkv,  g_bqkv);
    cudaGetSymbolAddress((void**)&x1h,   g_x1h);
    cudaGetSymbolAddress((void**)&x2h,   g_x2h);
    cudaGetSymbolAddress((void**)&qkv,   g_qkv);
    cudaGetSymbolAddress((void**)&kv2,   g_kv2);
    cudaGetSymbolAddress((void**)&ctx,   g_ctx);
    cudaGetSymbolAddress((void**)&tmp,   g_tmp);
    cudaGetSymbolAddress((void**)&o1f,   g_o1f);
    cudaGetSymbolAddress((void**)&o1h,   g_o1h);
    cudaGetSymbolAddress((void**)&hid,   g_hid);
    cudaGetSymbolAddress((void**)&bm1,   g_bm1);
    cudaGetSymbolAddress((void**)&bm2,   g_bm2);

    cudaFuncSetAttribute(proj_kernel, cudaFuncAttributeMaxDynamicSharedMemorySize, GSMEM_BYTES);
    cudaFuncSetAttribute(gemm_h<0,0>, cudaFuncAttributeMaxDynamicSharedMemorySize, GSMEM_BYTES);
    cudaFuncSetAttribute(gemm_h<1,1>, cudaFuncAttributeMaxDynamicSharedMemorySize, GSMEM_BYTES);
    cudaFuncSetAttribute(attn_kernel, cudaFuncAttributeMaxDynamicSharedMemorySize, ATT_SMEM_BYTES);

    const int M = CB * CN1;

    pack_weights<<<dim3(32, 32, 6), dim3(32, 8)>>>(Wq, Wk, Wv, Wo, W1, W2,
                                                   wqkvT, woT, w1T, w2T);
    pack_misc<<<M * CD / 256, 256>>>(x1, x2, bq, bk, bv, x1h, x2h, bqkv);
    build_bm<<<4096 + CB, 256>>>(adj1, mask1, mask2, bm1, bm2);

    // merged qkv + kv2 projection (2560 CTAs)
    proj_kernel<<<dim3(10, M / BM), 128, GSMEM_BYTES>>>(x1h, x2h, wqkvT, bqkv, qkv, kv2);

    attn_kernel<<<dim3(CN1 / 128, CH, CB), 256, ATT_SMEM_BYTES>>>(qkv, kv2, bm1, bm2, ctx);

    gemm_h<0,0><<<dim3(2, M / BM), 128, GSMEM_BYTES>>>(ctx, woT, bo, tmp, CD, CD);
    add_ln_kernel<1><<<M / 8, 256>>>(x1, tmp, g1, be1, o1f, o1h);

    gemm_h<1,1><<<dim3(8, M / BM), 128, GSMEM_BYTES>>>(o1h, w1T, b1, hid, CDFF, CD);
    gemm_h<0,0><<<dim3(2, M / BM), 128, GSMEM_BYTES>>>(hid, w2T, b2, tmp, CD, CDFF);
    add_ln_kernel<0><<<M / 8, 256>>>(o1f, tmp, g2, be2, out, nullptr);
}

// round 15
// speedup vs baseline: 1.1176x; 1.0112x over previous
#include <cuda_runtime.h>
#include <cuda_fp16.h>
#include <cstdint>

#define CB   128
#define CN1  256
#define CN2  256
#define CD   256
#define CH   8
#define CDH  32
#define CDFF 1024

// ---------------- scratch (device globals) ----------------
__device__ __half g_wqkvT[768 * CD];      // [N][K] half, q-part pre-scaled
__device__ __half g_woT  [CD * CD];
__device__ __half g_w1T  [CDFF * CD];
__device__ __half g_w2T  [CD * CDFF];
__device__ float  g_bqkv [768];
__device__ __half g_x1h  [CB * CN1 * CD];
__device__ __half g_x2h  [CB * CN2 * CD];
__device__ __half g_qkv  [CB * CN1 * 768];
__device__ __half g_kv2  [CB * CN2 * 512];
__device__ __half g_ctx  [CB * CN1 * CD];
__device__ __half g_tmph [CB * CN1 * CD];       // half scratch (wo / ffn2 out)
__device__ __half g_o1h  [CB * CN1 * CD];
__device__ __half g_hid  [CB * CN1 * CDFF];
__device__ uint32_t g_bm1[CB * CN1 * 8];
__device__ uint32_t g_bm2[CB * 8];

#define QSCALE (0.17677669529663687f * 1.4426950408889634f)

// ---------------- helpers ----------------
__device__ __forceinline__ void cp16(void* s, const void* g) {
    unsigned sa = (unsigned)__cvta_generic_to_shared(s);
    asm volatile("cp.async.cg.shared.global [%0], [%1], 16;\n" :: "r"(sa), "l"(g));
}
__device__ __forceinline__ void cp_commit() { asm volatile("cp.async.commit_group;\n"); }
template <int N> __device__ __forceinline__ void cp_wait() {
    asm volatile("cp.async.wait_group %0;\n" :: "n"(N));
}
__device__ __forceinline__ void mma16816(float* d, const uint32_t* a, const uint32_t* b) {
    asm volatile(
        "mma.sync.aligned.m16n8k16.row.col.f32.f16.f16.f32 "
        "{%0,%1,%2,%3}, {%4,%5,%6,%7}, {%8,%9}, {%0,%1,%2,%3};"
        : "+f"(d[0]), "+f"(d[1]), "+f"(d[2]), "+f"(d[3])
        : "r"(a[0]), "r"(a[1]), "r"(a[2]), "r"(a[3]), "r"(b[0]), "r"(b[1]));
}
__device__ __forceinline__ void ldsm4(uint32_t* r, const __half* p) {
    uint32_t a = (uint32_t)__cvta_generic_to_shared(p);
    asm volatile("ldmatrix.sync.aligned.m8n8.x4.shared.b16 {%0,%1,%2,%3}, [%4];"
                 : "=r"(r[0]), "=r"(r[1]), "=r"(r[2]), "=r"(r[3]) : "r"(a));
}
__device__ __forceinline__ void ldsm4t(uint32_t* r, const __half* p) {
    uint32_t a = (uint32_t)__cvta_generic_to_shared(p);
    asm volatile("ldmatrix.sync.aligned.m8n8.x4.trans.shared.b16 {%0,%1,%2,%3}, [%4];"
                 : "=r"(r[0]), "=r"(r[1]), "=r"(r[2]), "=r"(r[3]) : "r"(a));
}
__device__ __forceinline__ float ex2f(float x) {
    float y; asm("ex2.approx.f32 %0, %1;" : "=f"(y) : "f"(x)); return y;
}
__device__ __forceinline__ uint32_t f22u(float a, float b) {
    __half2 h = __floats2half2_rn(a, b);
    return *(uint32_t*)&h;
}

// ============================================================================
// fp16 GEMM body (exact R14): block 128x128x64, 4 warps, warp 64x64,
// m16n8k16, ldmatrix, 3-stage cp.async (depth-2 prefetch), runtime N/K.
// ============================================================================
#define BM 128
#define BN 128
#define BK 64
#define APADH 72
#define STGH (2 * 128 * APADH)
#define GS 3
#define GSMEM_BYTES (GS * STGH * 2)               // 110592

template <int EPI, int OUTH>
__device__ __forceinline__ void gemm_body(
    const __half* __restrict__ A, const __half* __restrict__ WT,
    const float* __restrict__ bias, void* __restrict__ Cv,
    __half* smh, int m0, int n0, int N, int K, int tid)
{
    const int warp = tid >> 5;
    const int lane = tid & 31;
    const int wm   = warp & 1;
    const int wn   = warp >> 1;
    const int kt   = K / BK;
    const int qr   = lane >> 2;
    const int qc   = lane & 3;
    const int arow = (lane & 7) + 8 * ((lane >> 3) & 1);
    const int acol = 8 * (lane >> 4);
    const int brow = (lane & 7) + 8 * (lane >> 4);
    const int bcol = 8 * ((lane >> 3) & 1);

    auto stageSlot = [&](int t) -> __half* {
        int s = t % GS;
        return smh + s * STGH;
    };

    auto loadStage = [&](int t) {
        __half* As = stageSlot(t);
        __half* Bs = As + 128 * APADH;
        const int k0 = t * BK;
#pragma unroll
        for (int j = 0; j < 8; j++) {
            int i = tid + j * 128;
            int r = i >> 3, c8 = (i & 7) * 8;
            cp16(As + r * APADH + c8, A + (size_t)(m0 + r) * K + k0 + c8);
        }
#pragma unroll
        for (int j = 0; j < 8; j++) {
            int i = tid + j * 128;
            int r = i >> 3, c8 = (i & 7) * 8;
            cp16(Bs + r * APADH + c8, WT + (size_t)(n0 + r) * K + k0 + c8);
        }
        cp_commit();
    };

    float acc[4][8][4];
#pragma unroll
    for (int mt = 0; mt < 4; mt++)
#pragma unroll
        for (int nt = 0; nt < 8; nt++)
#pragma unroll
            for (int e = 0; e < 4; e++) acc[mt][nt][e] = 0.0f;

    loadStage(0);
    loadStage(1);

    for (int t = 0; t < kt; t++) {
        if (t + 1 < kt) cp_wait<1>(); else cp_wait<0>();
        __syncthreads();
        if (t + 2 < kt) loadStage(t + 2);

        const __half* As = stageSlot(t) + (wm * 64) * APADH;
        const __half* Bs = stageSlot(t) + 128 * APADH + (wn * 64) * APADH;
#pragma unroll
        for (int kk = 0; kk < BK; kk += 16) {
            uint32_t af[4][4];
            uint32_t bf[4][4];
#pragma unroll
            for (int mt = 0; mt < 4; mt++)
                ldsm4(af[mt], As + (mt * 16 + arow) * APADH + kk + acol);
#pragma unroll
            for (int p = 0; p < 4; p++)
                ldsm4(bf[p], Bs + (p * 16 + brow) * APADH + kk + bcol);
#pragma unroll
            for (int mt = 0; mt < 4; mt++)
#pragma unroll
                for (int nt = 0; nt < 8; nt++)
                    mma16816(acc[mt][nt], af[mt], &bf[nt >> 1][(nt & 1) * 2]);
        }
    }

    // register -> global epilogue
#pragma unroll
    for (int nt = 0; nt < 8; nt++) {
        const int col = n0 + wn * 64 + nt * 8 + qc * 2;
        const float2 bv = *(const float2*)(bias + col);
#pragma unroll
        for (int mt = 0; mt < 4; mt++) {
            const int row = m0 + wm * 64 + mt * 16 + qr;
            float a0 = acc[mt][nt][0] + bv.x, a1 = acc[mt][nt][1] + bv.y;
            float a2 = acc[mt][nt][2] + bv.x, a3 = acc[mt][nt][3] + bv.y;
            if (EPI == 1) {
                a0 = fmaxf(a0, 0.f); a1 = fmaxf(a1, 0.f);
                a2 = fmaxf(a2, 0.f); a3 = fmaxf(a3, 0.f);
            }
            if (OUTH) {
                __half* C = (__half*)Cv;
                *(uint32_t*)(C + (size_t)row * N + col)       = f22u(a0, a1);
                *(uint32_t*)(C + (size_t)(row + 8) * N + col) = f22u(a2, a3);
            } else {
                float* C = (float*)Cv;
                *(float2*)(C + (size_t)row * N + col)       = make_float2(a0, a1);
                *(float2*)(C + (size_t)(row + 8) * N + col) = make_float2(a2, a3);
            }
        }
    }
}

// merged qkv + kv2 projection: grid.x = 10 (6 qkv tiles + 4 kv2 tiles)
__global__ __launch_bounds__(128, 2)
void proj_kernel(const __half* __restrict__ x1h, const __half* __restrict__ x2h,
                 const __half* __restrict__ wqkvT, const float* __restrict__ bqkv,
                 __half* __restrict__ qkv, __half* __restrict__ kv2)
{
    extern __shared__ __half smh[];
    const int bx = blockIdx.x;
    const int m0 = blockIdx.y * BM;
    if (bx < 6)
        gemm_body<0, 1>(x1h, wqkvT, bqkv, qkv, smh, m0, bx * 128, 768, 256, threadIdx.x);
    else
        gemm_body<0, 1>(x2h, wqkvT + 256 * CD, bqkv + 256, kv2, smh,
                        m0, (bx - 6) * 128, 512, 256, threadIdx.x);
}

template <int EPI, int OUTH>
__global__ __launch_bounds__(128, 2)
void gemm_h(const __half* __restrict__ A, const __half* __restrict__ WT,
            const float* __restrict__ bias, void* __restrict__ Cv, int N, int K)
{
    extern __shared__ __half smh[];
    gemm_body<EPI, OUTH>(A, WT, bias, Cv, smh,
                         blockIdx.y * BM, blockIdx.x * BN, N, K, threadIdx.x);
}

// ============================================================================
// FlashAttention-style dual-source graph attention (exact R7/R12/R14 version).
// ============================================================================
#define KPADH 40
#define SM_K_H   (256 * KPADH)
#define SM_V_H   (256 * KPADH)
#define ATT_BM_OFF ((SM_K_H + SM_V_H) * 2)
#define ATT_SMEM_BYTES (ATT_BM_OFF + (1024 + 8) * 4)

__global__ __launch_bounds__(256, 2)
void attn_kernel(const __half* __restrict__ qkv, const __half* __restrict__ kv2,
                 const uint32_t* __restrict__ bm1, const uint32_t* __restrict__ bm2,
                 __half* __restrict__ ctx)
{
    extern __shared__ __half smh[];
    __half* sK = smh;
    __half* sV = sK + SM_K_H;
    uint32_t* sBM  = (uint32_t*)((char*)smh + ATT_BM_OFF);
    uint32_t* sBM2 = sBM + 1024;

    const int b  = blockIdx.z;
    const int h  = blockIdx.y;
    const int q0 = blockIdx.x * 128;
    const int tid  = threadIdx.x;
    const int warp = tid >> 5;
    const int lane = tid & 31;
    const int qr   = lane >> 2;
    const int qc   = lane & 3;
    const int arow = (lane & 7) + 8 * ((lane >> 3) & 1);
    const int acol = 8 * (lane >> 4);
    const int brow = (lane & 7) + 8 * (lane >> 4);
    const int bcol = 8 * ((lane >> 3) & 1);

#pragma unroll
    for (int j = 0; j < 4; j++) {
        int i = tid + j * 256;
        sBM[i] = bm1[((size_t)(b * CN1) + q0 + (i >> 3)) * 8 + (i & 7)];
    }
    if (tid < 8) sBM2[tid] = bm2[b * 8 + tid];

    uint32_t qf[2][4];
    {
        const __half* Qb = qkv + (size_t)(b * CN1 + q0 + warp * 16) * 768 + h * CDH;
#pragma unroll
        for (int kc = 0; kc < 2; kc++) {
            const __half* p = Qb + kc * 16 + 2 * qc;
            qf[kc][0] = *(const uint32_t*)(p + (size_t)qr * 768);
            qf[kc][1] = *(const uint32_t*)(p + (size_t)(qr + 8) * 768);
            qf[kc][2] = *(const uint32_t*)(p + (size_t)qr * 768 + 8);
            qf[kc][3] = *(const uint32_t*)(p + (size_t)(qr + 8) * 768 + 8);
        }
    }

    float ofin[4][4];
#pragma unroll
    for (int n = 0; n < 4; n++)
#pragma unroll
        for (int e = 0; e < 4; e++) ofin[n][e] = 0.0f;

#pragma unroll 1
    for (int src = 0; src < 2; src++) {
        const __half* base = src ? kv2 : qkv;
        const int stride  = src ? 512 : 768;
        const int koff    = src ? 0   : 256;
        const int voff    = src ? 256 : 512;

        __syncthreads();
#pragma unroll
        for (int j = 0; j < 4; j++) {
            int i = tid + j * 256;
            int r = i >> 2, c8 = (i & 3) * 8;
            const __half* row = base + (size_t)(b * 256 + r) * stride + h * CDH;
            *(uint4*)(sK + r * KPADH + c8) = *(const uint4*)(row + koff + c8);
            *(uint4*)(sV + r * KPADH + c8) = *(const uint4*)(row + voff + c8);
        }
        __syncthreads();

        float m0 = -1e30f, m1 = -1e30f, l0 = 0.0f, l1 = 0.0f;
        float o[4][4];
#pragma unroll
        for (int n = 0; n < 4; n++)
#pragma unroll
            for (int e = 0; e < 4; e++) o[n][e] = 0.0f;

#pragma unroll 1
        for (int chunk = 0; chunk < 4; chunk++) {
            const int key0 = chunk * 64;

            float s[8][4];
#pragma unroll
            for (int nf = 0; nf < 8; nf++)
                s[nf][0] = s[nf][1] = s[nf][2] = s[nf][3] = 0.0f;
#pragma unroll
            for (int pr = 0; pr < 4; pr++) {
                const __half* kbase = sK + (size_t)(key0 + pr * 16 + brow) * KPADH + bcol;
                uint32_t kb0[4], kb1[4];
                ldsm4(kb0, kbase);
                ldsm4(kb1, kbase + 16);
                mma16816(s[2 * pr],     qf[0], kb0 + 0);
                mma16816(s[2 * pr],     qf[1], kb1 + 0);
                mma16816(s[2 * pr + 1], qf[0], kb0 + 2);
                mma16816(s[2 * pr + 1], qf[1], kb1 + 2);
            }

            uint32_t wa0, wa1, wb0, wb1;
            if (src == 0) {
                const uint32_t* ra = sBM + (warp * 16 + qr) * 8 + chunk * 2;
                const uint32_t* rb = sBM + (warp * 16 + qr + 8) * 8 + chunk * 2;
                wa0 = ra[0]; wa1 = ra[1]; wb0 = rb[0]; wb1 = rb[1];
            } else {
                wa0 = sBM2[chunk * 2]; wa1 = sBM2[chunk * 2 + 1];
                wb0 = wa0; wb1 = wa1;
            }
            float cm0 = -1e30f, cm1 = -1e30f;
#pragma unroll
            for (int nf = 0; nf < 8; nf++) {
                const int sh = (nf & 3) * 8 + qc * 2;
                const uint32_t ba = ((nf < 4 ? wa0 : wa1) >> sh);
                const uint32_t bb = ((nf < 4 ? wb0 : wb1) >> sh);
                s[nf][0] = (ba & 1u) ? s[nf][0] : -1e9f;
                s[nf][1] = (ba & 2u) ? s[nf][1] : -1e9f;
                s[nf][2] = (bb & 1u) ? s[nf][2] : -1e9f;
                s[nf][3] = (bb & 2u) ? s[nf][3] : -1e9f;
                cm0 = fmaxf(cm0, fmaxf(s[nf][0], s[nf][1]));
                cm1 = fmaxf(cm1, fmaxf(s[nf][2], s[nf][3]));
            }
            cm0 = fmaxf(cm0, __shfl_xor_sync(0xffffffffu, cm0, 1));
            cm0 = fmaxf(cm0, __shfl_xor_sync(0xffffffffu, cm0, 2));
            cm1 = fmaxf(cm1, __shfl_xor_sync(0xffffffffu, cm1, 1));
            cm1 = fmaxf(cm1, __shfl_xor_sync(0xffffffffu, cm1, 2));

            const float mn0 = fmaxf(m0, cm0), mn1 = fmaxf(m1, cm1);
            const float f0 = ex2f(m0 - mn0), f1 = ex2f(m1 - mn1);
            m0 = mn0; m1 = mn1;
            l0 *= f0; l1 *= f1;
#pragma unroll
            for (int n = 0; n < 4; n++) {
                o[n][0] *= f0; o[n][1] *= f0;
                o[n][2] *= f1; o[n][3] *= f1;
            }

#pragma unroll
            for (int nf = 0; nf < 8; nf++) {
                s[nf][0] = ex2f(s[nf][0] - mn0);
                s[nf][1] = ex2f(s[nf][1] - mn0);
                s[nf][2] = ex2f(s[nf][2] - mn1);
                s[nf][3] = ex2f(s[nf][3] - mn1);
                l0 += s[nf][0] + s[nf][1];
                l1 += s[nf][2] + s[nf][3];
            }

#pragma unroll
            for (int j = 0; j < 4; j++) {
                uint32_t ap[4];
                ap[0] = f22u(s[2*j][0],   s[2*j][1]);
                ap[1] = f22u(s[2*j][2],   s[2*j][3]);
                ap[2] = f22u(s[2*j+1][0], s[2*j+1][1]);
                ap[3] = f22u(s[2*j+1][2], s[2*j+1][3]);
                const __half* vbase = sV + (size_t)(key0 + j * 16 + arow) * KPADH + acol;
                uint32_t vb0[4], vb1[4];
                ldsm4t(vb0, vbase);
                ldsm4t(vb1, vbase + 16);
                mma16816(o[0], ap, vb0 + 0);
                mma16816(o[1], ap, vb0 + 2);
                mma16816(o[2], ap, vb1 + 0);
                mma16816(o[3], ap, vb1 + 2);
            }
        }

        l0 += __shfl_xor_sync(0xffffffffu, l0, 1);
        l0 += __shfl_xor_sync(0xffffffffu, l0, 2);
        l1 += __shfl_xor_sync(0xffffffffu, l1, 1);
        l1 += __shfl_xor_sync(0xffffffffu, l1, 2);
        const float i0 = 1.0f / l0, i1 = 1.0f / l1;
#pragma unroll
        for (int n = 0; n < 4; n++) {
            ofin[n][0] += o[n][0] * i0;
            ofin[n][1] += o[n][1] * i0;
            ofin[n][2] += o[n][2] * i1;
            ofin[n][3] += o[n][3] * i1;
        }
    }

    __half* outA = ctx + (size_t)(b * CN1 + q0 + warp * 16 + qr) * CD + h * CDH + qc * 2;
    __half* outB = outA + 8 * CD;
#pragma unroll
    for (int n = 0; n < 4; n++) {
        *(uint32_t*)(outA + n * 8) = f22u(ofin[n][0], ofin[n][1]);
        *(uint32_t*)(outB + n * 8) = f22u(ofin[n][2], ofin[n][3]);
    }
}

// ============================================================================
// LayerNorm variants (fp32 math):
//   XH=0: X fp32;  XH=1: X half.   Y is always half.
//   WF=1: write fp32 out;  WHm=1: write half mirror.
// ============================================================================
template <int XH, int WF, int WHm>
__global__ __launch_bounds__(256)
void add_ln_kernel(const void* __restrict__ Xv, const __half* __restrict__ Y,
                   const float* __restrict__ g, const float* __restrict__ be,
                   float* __restrict__ outF, __half* __restrict__ outH)
{
    const int warp = threadIdx.x >> 5;
    const int lane = threadIdx.x & 31;
    const size_t row = (size_t)blockIdx.x * 8 + warp;
    float v[8];
    float s = 0.0f;
#pragma unroll
    for (int i = 0; i < 8; i++) {
        int c = lane + i * 32;
        float xv = XH ? __half2float(((const __half*)Xv)[row * CD + c])
                      : ((const float*)Xv)[row * CD + c];
        v[i] = xv + __half2float(Y[row * CD + c]);
        s += v[i];
    }
#pragma unroll
    for (int o = 16; o > 0; o >>= 1) s += __shfl_xor_sync(0xffffffffu, s, o);
    const float mu = s * (1.0f / CD);
    float s2 = 0.0f;
#pragma unroll
    for (int i = 0; i < 8; i++) { float d = v[i] - mu; s2 += d * d; }
#pragma unroll
    for (int o = 16; o > 0; o >>= 1) s2 += __shfl_xor_sync(0xffffffffu, s2, o);
    const float inv = rsqrtf(s2 * (1.0f / CD) + 1e-6f);
#pragma unroll
    for (int i = 0; i < 8; i++) {
        int c = lane + i * 32;
        float r = g[c] * (v[i] - mu) * inv + be[c];
        if (WF)  outF[row * CD + c] = r;
        if (WHm) outH[row * CD + c] = __float2half(r);
    }
}

// ============================================================================
// packing kernels (exact R14 versions)
// ============================================================================
__global__ void pack_weights(const float* __restrict__ Wq, const float* __restrict__ Wk,
                             const float* __restrict__ Wv, const float* __restrict__ Wo,
                             const float* __restrict__ W1, const float* __restrict__ W2,
                             __half* __restrict__ wqkvT, __half* __restrict__ woT,
                             __half* __restrict__ w1T,  __half* __restrict__ w2T)
{
    __shared__ float tile[32][33];
    const int z = blockIdx.z;
    const float* src; __half* dst; int K, N; float scale = 1.0f;
    switch (z) {
        case 0: src = Wq; dst = wqkvT;            K = CD;   N = CD;   scale = QSCALE; break;
        case 1: src = Wk; dst = wqkvT + 256 * CD; K = CD;   N = CD;   break;
        case 2: src = Wv; dst = wqkvT + 512 * CD; K = CD;   N = CD;   break;
        case 3: src = Wo; dst = woT;              K = CD;   N = CD;   break;
        case 4: src = W1; dst = w1T;              K = CD;   N = CDFF; break;
        default: src = W2; dst = w2T;             K = CDFF; N = CD;   break;
    }
    const int k0 = blockIdx.y * 32, n0 = blockIdx.x * 32;
    if (k0 >= K || n0 >= N) return;
    const int tx = threadIdx.x, ty = threadIdx.y;
#pragma unroll
    for (int i = 0; i < 32; i += 8) tile[ty + i][tx] = src[(size_t)(k0 + ty + i) * N + n0 + tx];
    __syncthreads();
#pragma unroll
    for (int i = 0; i < 32; i += 8)
        dst[(size_t)(n0 + ty + i) * K + k0 + tx] = __float2half(tile[tx][ty + i] * scale);
}

__global__ void pack_misc(const float* __restrict__ x1, const float* __restrict__ x2,
                          const float* __restrict__ bq, const float* __restrict__ bk,
                          const float* __restrict__ bv,
                          __half* __restrict__ x1h, __half* __restrict__ x2h,
                          float* __restrict__ bqkv)
{
    const size_t i = (size_t)blockIdx.x * 256 + threadIdx.x;
    x1h[i] = __float2half(x1[i]);
    x2h[i] = __float2half(x2[i]);
    if (i < 256) {
        bqkv[i]       = bq[i] * QSCALE;
        bqkv[256 + i] = bk[i];
        bqkv[512 + i] = bv[i];
    }
}

__global__ void build_bm(const float* __restrict__ adj, const float* __restrict__ mask1,
                         const float* __restrict__ mask2,
                         uint32_t* __restrict__ bm1, uint32_t* __restrict__ bm2)
{
    const int lane = threadIdx.x & 31;
    if (blockIdx.x < 4096) {
        const int gw = (blockIdx.x * 256 + threadIdx.x) >> 5;
        const int b = gw >> 8;
        const float* arow = adj + (size_t)gw * 256;
        const float* m1 = mask1 + (size_t)b * 256;
#pragma unroll
        for (int w = 0; w < 8; w++) {
            float v = arow[w * 32 + lane] * m1[w * 32 + lane];
            uint32_t bits = __ballot_sync(0xffffffffu, v > 0.0f);
            if (lane == 0) bm1[(size_t)gw * 8 + w] = bits;
        }
    } else {
        const int b = blockIdx.x - 4096;
        const int w = threadIdx.x >> 5;
        float v = mask2[(size_t)b * 256 + w * 32 + lane];
        uint32_t bits = __ballot_sync(0xffffffffu, v > 0.0f);
        if (lane == 0) bm2[b * 8 + w] = bits;
    }
}

// ============================================================================
// Host launch
// ============================================================================
extern "C" void kernel_launch(void* const* d_in, const int* in_sizes, int n_in,
                              void* d_out, int out_size)
{
    const float* x1    = (const float*)d_in[0];
    const float* adj1  = (const float*)d_in[1];
    const float* mask1 = (const float*)d_in[2];
    const float* x2    = (const float*)d_in[3];
    const float* mask2 = (const float*)d_in[4];
    const float* Wq = (const float*)d_in[5];  const float* bq = (const float*)d_in[6];
    const float* Wk = (const float*)d_in[7];  const float* bk = (const float*)d_in[8];
    const float* Wv = (const float*)d_in[9];  const float* bv = (const float*)d_in[10];
    const float* Wo = (const float*)d_in[11]; const float* bo = (const float*)d_in[12];
    const float* W1 = (const float*)d_in[13]; const float* b1 = (const float*)d_in[14];
    const float* W2 = (const float*)d_in[15]; const float* b2 = (const float*)d_in[16];
    const float* g1 = (const float*)d_in[17]; const float* be1 = (const float*)d_in[18];
    const float* g2 = (const float*)d_in[19]; const float* be2 = (const float*)d_in[20];
    float* out = (float*)d_out;

    __half *wqkvT, *woT, *w1T, *w2T, *x1h, *x2h, *qkv, *kv2, *ctx, *tmph, *o1h, *hid;
    float *bqkv;
    uint32_t *bm1, *bm2;
    cudaGetSymbolAddress((void**)&wqkvT, g_wqkvT);
    cudaGetSymbolAddress((void**)&woT,   g_woT);
    cudaGetSymbolAddress((void**)&w1T,   g_w1T);
    cudaGetSymbolAddress((void**)&w2T,   g_w2T);
    cudaGetSymbolAddress((void**)&bqkv,  g_bqkv);
    cudaGetSymbolAddress((void**)&x1h,   g_x1h);
    cudaGetSymbolAddress((void**)&x2h,   g_x2h);
    cudaGetSymbolAddress((void**)&qkv,   g_qkv);
    cudaGetSymbolAddress((void**)&kv2,   g_kv2);
    cudaGetSymbolAddress((void**)&ctx,   g_ctx);
    cudaGetSymbolAddress((void**)&tmph,  g_tmph);
    cudaGetSymbolAddress((void**)&o1h,   g_o1h);
    cudaGetSymbolAddress((void**)&hid,   g_hid);
    cudaGetSymbolAddress((void**)&bm1,   g_bm1);
    cudaGetSymbolAddress((void**)&bm2,   g_bm2);

    cudaFuncSetAttribute(proj_kernel, cudaFuncAttributeMaxDynamicSharedMemorySize, GSMEM_BYTES);
    cudaFuncSetAttribute(gemm_h<0,1>, cudaFuncAttributeMaxDynamicSharedMemorySize, GSMEM_BYTES);
    cudaFuncSetAttribute(gemm_h<1,1>, cudaFuncAttributeMaxDynamicSharedMemorySize, GSMEM_BYTES);
    cudaFuncSetAttribute(attn_kernel, cudaFuncAttributeMaxDynamicSharedMemorySize, ATT_SMEM_BYTES);

    const int M = CB * CN1;

    pack_weights<<<dim3(32, 32, 6), dim3(32, 8)>>>(Wq, Wk, Wv, Wo, W1, W2,
                                                   wqkvT, woT, w1T, w2T);
    pack_misc<<<M * CD / 256, 256>>>(x1, x2, bq, bk, bv, x1h, x2h, bqkv);
    build_bm<<<4096 + CB, 256>>>(adj1, mask1, mask2, bm1, bm2);

    // merged qkv + kv2 projection (2560 CTAs)
    proj_kernel<<<dim3(10, M / BM), 128, GSMEM_BYTES>>>(x1h, x2h, wqkvT, bqkv, qkv, kv2);

    attn_kernel<<<dim3(CN1 / 128, CH, CB), 256, ATT_SMEM_BYTES>>>(qkv, kv2, bm1, bm2, ctx);

    // wo projection -> half tmp; LN1: X = x1 (fp32), Y = tmph -> o1h only
    gemm_h<0,1><<<dim3(2, M / BM), 128, GSMEM_BYTES>>>(ctx, woT, bo, tmph, CD, CD);
    add_ln_kernel<0,0,1><<<M / 8, 256>>>(x1, tmph, g1, be1, nullptr, o1h);

    // FFN (half throughout); LN2: X = o1h (half), Y = tmph -> fp32 out
    gemm_h<1,1><<<dim3(8, M / BM), 128, GSMEM_BYTES>>>(o1h, w1T, b1, hid, CDFF, CD);
    gemm_h<0,1><<<dim3(2, M / BM), 128, GSMEM_BYTES>>>(hid, w2T, b2, tmph, CD, CDFF);
    add_ln_kernel<1,1,0><<<M / 8, 256>>>(o1h, tmph, g2, be2, out, nullptr);
}

// round 16
// speedup vs baseline: 1.1280x; 1.0093x over previous
#include <cuda_runtime.h>
#include <cuda_fp16.h>
#include <cstdint>

#define CB   128
#define CN1  256
#define CN2  256
#define CD   256
#define CH   8
#define CDH  32
#define CDFF 1024

// ---------------- scratch (device globals) ----------------
__device__ __half g_wqkvT[768 * CD];      // [N][K] half, q-part pre-scaled
__device__ __half g_woT  [CD * CD];
__device__ __half g_w1T  [CDFF * CD];
__device__ __half g_w2T  [CD * CDFF];
__device__ float  g_bqkv [768];
__device__ __half g_x1h  [CB * CN1 * CD];
__device__ __half g_x2h  [CB * CN2 * CD];
__device__ __half g_qkv  [CB * CN1 * 768];
__device__ __half g_kv2  [CB * CN2 * 512];
__device__ __half g_ctx  [CB * CN1 * CD];
__device__ __half g_tmph [CB * CN1 * CD];
__device__ __half g_o1h  [CB * CN1 * CD];
__device__ __half g_hid  [CB * CN1 * CDFF];
__device__ uint32_t g_bm1[CB * CN1 * 8];
__device__ uint32_t g_bm2[CB * 8];

#define QSCALE (0.17677669529663687f * 1.4426950408889634f)

// ---------------- helpers ----------------
__device__ __forceinline__ void cp16(void* s, const void* g) {
    unsigned sa = (unsigned)__cvta_generic_to_shared(s);
    asm volatile("cp.async.cg.shared.global [%0], [%1], 16;\n" :: "r"(sa), "l"(g));
}
__device__ __forceinline__ void cp_commit() { asm volatile("cp.async.commit_group;\n"); }
template <int N> __device__ __forceinline__ void cp_wait() {
    asm volatile("cp.async.wait_group %0;\n" :: "n"(N));
}
__device__ __forceinline__ void mma16816(float* d, const uint32_t* a, const uint32_t* b) {
    asm volatile(
        "mma.sync.aligned.m16n8k16.row.col.f32.f16.f16.f32 "
        "{%0,%1,%2,%3}, {%4,%5,%6,%7}, {%8,%9}, {%0,%1,%2,%3};"
        : "+f"(d[0]), "+f"(d[1]), "+f"(d[2]), "+f"(d[3])
        : "r"(a[0]), "r"(a[1]), "r"(a[2]), "r"(a[3]), "r"(b[0]), "r"(b[1]));
}
__device__ __forceinline__ void ldsm4(uint32_t* r, const __half* p) {
    uint32_t a = (uint32_t)__cvta_generic_to_shared(p);
    asm volatile("ldmatrix.sync.aligned.m8n8.x4.shared.b16 {%0,%1,%2,%3}, [%4];"
                 : "=r"(r[0]), "=r"(r[1]), "=r"(r[2]), "=r"(r[3]) : "r"(a));
}
__device__ __forceinline__ void ldsm4t(uint32_t* r, const __half* p) {
    uint32_t a = (uint32_t)__cvta_generic_to_shared(p);
    asm volatile("ldmatrix.sync.aligned.m8n8.x4.trans.shared.b16 {%0,%1,%2,%3}, [%4];"
                 : "=r"(r[0]), "=r"(r[1]), "=r"(r[2]), "=r"(r[3]) : "r"(a));
}
__device__ __forceinline__ float ex2f(float x) {
    float y; asm("ex2.approx.f32 %0, %1;" : "=f"(y) : "f"(x)); return y;
}
__device__ __forceinline__ uint32_t f22u(float a, float b) {
    __half2 h = __floats2half2_rn(a, b);
    return *(uint32_t*)&h;
}

// ============================================================================
// fp16 GEMM body (exact R14/R15): block 128x128x64, 4 warps, warp 64x64,
// m16n8k16, ldmatrix, 3-stage cp.async (depth-2 prefetch), runtime N/K.
// ============================================================================
#define BM 128
#define BN 128
#define BK 64
#define APADH 72
#define STGH (2 * 128 * APADH)
#define GS 3
#define GSMEM_BYTES (GS * STGH * 2)               // 110592

template <int EPI, int OUTH>
__device__ __forceinline__ void gemm_body(
    const __half* __restrict__ A, const __half* __restrict__ WT,
    const float* __restrict__ bias, void* __restrict__ Cv,
    __half* smh, int m0, int n0, int N, int K, int tid)
{
    const int warp = tid >> 5;
    const int lane = tid & 31;
    const int wm   = warp & 1;
    const int wn   = warp >> 1;
    const int kt   = K / BK;
    const int qr   = lane >> 2;
    const int qc   = lane & 3;
    const int arow = (lane & 7) + 8 * ((lane >> 3) & 1);
    const int acol = 8 * (lane >> 4);
    const int brow = (lane & 7) + 8 * (lane >> 4);
    const int bcol = 8 * ((lane >> 3) & 1);

    auto stageSlot = [&](int t) -> __half* {
        int s = t % GS;
        return smh + s * STGH;
    };

    auto loadStage = [&](int t) {
        __half* As = stageSlot(t);
        __half* Bs = As + 128 * APADH;
        const int k0 = t * BK;
#pragma unroll
        for (int j = 0; j < 8; j++) {
            int i = tid + j * 128;
            int r = i >> 3, c8 = (i & 7) * 8;
            cp16(As + r * APADH + c8, A + (size_t)(m0 + r) * K + k0 + c8);
        }
#pragma unroll
        for (int j = 0; j < 8; j++) {
            int i = tid + j * 128;
            int r = i >> 3, c8 = (i & 7) * 8;
            cp16(Bs + r * APADH + c8, WT + (size_t)(n0 + r) * K + k0 + c8);
        }
        cp_commit();
    };

    float acc[4][8][4];
#pragma unroll
    for (int mt = 0; mt < 4; mt++)
#pragma unroll
        for (int nt = 0; nt < 8; nt++)
#pragma unroll
            for (int e = 0; e < 4; e++) acc[mt][nt][e] = 0.0f;

    loadStage(0);
    loadStage(1);

    for (int t = 0; t < kt; t++) {
        if (t + 1 < kt) cp_wait<1>(); else cp_wait<0>();
        __syncthreads();
        if (t + 2 < kt) loadStage(t + 2);

        const __half* As = stageSlot(t) + (wm * 64) * APADH;
        const __half* Bs = stageSlot(t) + 128 * APADH + (wn * 64) * APADH;
#pragma unroll
        for (int kk = 0; kk < BK; kk += 16) {
            uint32_t af[4][4];
            uint32_t bf[4][4];
#pragma unroll
            for (int mt = 0; mt < 4; mt++)
                ldsm4(af[mt], As + (mt * 16 + arow) * APADH + kk + acol);
#pragma unroll
            for (int p = 0; p < 4; p++)
                ldsm4(bf[p], Bs + (p * 16 + brow) * APADH + kk + bcol);
#pragma unroll
            for (int mt = 0; mt < 4; mt++)
#pragma unroll
                for (int nt = 0; nt < 8; nt++)
                    mma16816(acc[mt][nt], af[mt], &bf[nt >> 1][(nt & 1) * 2]);
        }
    }

    // register -> global epilogue
#pragma unroll
    for (int nt = 0; nt < 8; nt++) {
        const int col = n0 + wn * 64 + nt * 8 + qc * 2;
        const float2 bv = *(const float2*)(bias + col);
#pragma unroll
        for (int mt = 0; mt < 4; mt++) {
            const int row = m0 + wm * 64 + mt * 16 + qr;
            float a0 = acc[mt][nt][0] + bv.x, a1 = acc[mt][nt][1] + bv.y;
            float a2 = acc[mt][nt][2] + bv.x, a3 = acc[mt][nt][3] + bv.y;
            if (EPI == 1) {
                a0 = fmaxf(a0, 0.f); a1 = fmaxf(a1, 0.f);
                a2 = fmaxf(a2, 0.f); a3 = fmaxf(a3, 0.f);
            }
            if (OUTH) {
                __half* C = (__half*)Cv;
                *(uint32_t*)(C + (size_t)row * N + col)       = f22u(a0, a1);
                *(uint32_t*)(C + (size_t)(row + 8) * N + col) = f22u(a2, a3);
            } else {
                float* C = (float*)Cv;
                *(float2*)(C + (size_t)row * N + col)       = make_float2(a0, a1);
                *(float2*)(C + (size_t)(row + 8) * N + col) = make_float2(a2, a3);
            }
        }
    }
}

// merged qkv + kv2 projection: grid.x = 10 (6 qkv tiles + 4 kv2 tiles)
__global__ __launch_bounds__(128, 2)
void proj_kernel(const __half* __restrict__ x1h, const __half* __restrict__ x2h,
                 const __half* __restrict__ wqkvT, const float* __restrict__ bqkv,
                 __half* __restrict__ qkv, __half* __restrict__ kv2)
{
    extern __shared__ __half smh[];
    const int bx = blockIdx.x;
    const int m0 = blockIdx.y * BM;
    if (bx < 6)
        gemm_body<0, 1>(x1h, wqkvT, bqkv, qkv, smh, m0, bx * 128, 768, 256, threadIdx.x);
    else
        gemm_body<0, 1>(x2h, wqkvT + 256 * CD, bqkv + 256, kv2, smh,
                        m0, (bx - 6) * 128, 512, 256, threadIdx.x);
}

template <int EPI, int OUTH>
__global__ __launch_bounds__(128, 2)
void gemm_h(const __half* __restrict__ A, const __half* __restrict__ WT,
            const float* __restrict__ bias, void* __restrict__ Cv, int N, int K)
{
    extern __shared__ __half smh[];
    gemm_body<EPI, OUTH>(A, WT, bias, Cv, smh,
                         blockIdx.y * BM, blockIdx.x * BN, N, K, threadIdx.x);
}

// ============================================================================
// FlashAttention-style dual-source graph attention (exact R7/R12/R14 version).
// ============================================================================
#define KPADH 40
#define SM_K_H   (256 * KPADH)
#define SM_V_H   (256 * KPADH)
#define ATT_BM_OFF ((SM_K_H + SM_V_H) * 2)
#define ATT_SMEM_BYTES (ATT_BM_OFF + (1024 + 8) * 4)

__global__ __launch_bounds__(256, 2)
void attn_kernel(const __half* __restrict__ qkv, const __half* __restrict__ kv2,
                 const uint32_t* __restrict__ bm1, const uint32_t* __restrict__ bm2,
                 __half* __restrict__ ctx)
{
    extern __shared__ __half smh[];
    __half* sK = smh;
    __half* sV = sK + SM_K_H;
    uint32_t* sBM  = (uint32_t*)((char*)smh + ATT_BM_OFF);
    uint32_t* sBM2 = sBM + 1024;

    const int b  = blockIdx.z;
    const int h  = blockIdx.y;
    const int q0 = blockIdx.x * 128;
    const int tid  = threadIdx.x;
    const int warp = tid >> 5;
    const int lane = tid & 31;
    const int qr   = lane >> 2;
    const int qc   = lane & 3;
    const int arow = (lane & 7) + 8 * ((lane >> 3) & 1);
    const int acol = 8 * (lane >> 4);
    const int brow = (lane & 7) + 8 * (lane >> 4);
    const int bcol = 8 * ((lane >> 3) & 1);

#pragma unroll
    for (int j = 0; j < 4; j++) {
        int i = tid + j * 256;
        sBM[i] = bm1[((size_t)(b * CN1) + q0 + (i >> 3)) * 8 + (i & 7)];
    }
    if (tid < 8) sBM2[tid] = bm2[b * 8 + tid];

    uint32_t qf[2][4];
    {
        const __half* Qb = qkv + (size_t)(b * CN1 + q0 + warp * 16) * 768 + h * CDH;
#pragma unroll
        for (int kc = 0; kc < 2; kc++) {
            const __half* p = Qb + kc * 16 + 2 * qc;
            qf[kc][0] = *(const uint32_t*)(p + (size_t)qr * 768);
            qf[kc][1] = *(const uint32_t*)(p + (size_t)(qr + 8) * 768);
            qf[kc][2] = *(const uint32_t*)(p + (size_t)qr * 768 + 8);
            qf[kc][3] = *(const uint32_t*)(p + (size_t)(qr + 8) * 768 + 8);
        }
    }

    float ofin[4][4];
#pragma unroll
    for (int n = 0; n < 4; n++)
#pragma unroll
        for (int e = 0; e < 4; e++) ofin[n][e] = 0.0f;

#pragma unroll 1
    for (int src = 0; src < 2; src++) {
        const __half* base = src ? kv2 : qkv;
        const int stride  = src ? 512 : 768;
        const int koff    = src ? 0   : 256;
        const int voff    = src ? 256 : 512;

        __syncthreads();
#pragma unroll
        for (int j = 0; j < 4; j++) {
            int i = tid + j * 256;
            int r = i >> 2, c8 = (i & 3) * 8;
            const __half* row = base + (size_t)(b * 256 + r) * stride + h * CDH;
            *(uint4*)(sK + r * KPADH + c8) = *(const uint4*)(row + koff + c8);
            *(uint4*)(sV + r * KPADH + c8) = *(const uint4*)(row + voff + c8);
        }
        __syncthreads();

        float m0 = -1e30f, m1 = -1e30f, l0 = 0.0f, l1 = 0.0f;
        float o[4][4];
#pragma unroll
        for (int n = 0; n < 4; n++)
#pragma unroll
            for (int e = 0; e < 4; e++) o[n][e] = 0.0f;

#pragma unroll 1
        for (int chunk = 0; chunk < 4; chunk++) {
            const int key0 = chunk * 64;

            float s[8][4];
#pragma unroll
            for (int nf = 0; nf < 8; nf++)
                s[nf][0] = s[nf][1] = s[nf][2] = s[nf][3] = 0.0f;
#pragma unroll
            for (int pr = 0; pr < 4; pr++) {
                const __half* kbase = sK + (size_t)(key0 + pr * 16 + brow) * KPADH + bcol;
                uint32_t kb0[4], kb1[4];
                ldsm4(kb0, kbase);
                ldsm4(kb1, kbase + 16);
                mma16816(s[2 * pr],     qf[0], kb0 + 0);
                mma16816(s[2 * pr],     qf[1], kb1 + 0);
                mma16816(s[2 * pr + 1], qf[0], kb0 + 2);
                mma16816(s[2 * pr + 1], qf[1], kb1 + 2);
            }

            uint32_t wa0, wa1, wb0, wb1;
            if (src == 0) {
                const uint32_t* ra = sBM + (warp * 16 + qr) * 8 + chunk * 2;
                const uint32_t* rb = sBM + (warp * 16 + qr + 8) * 8 + chunk * 2;
                wa0 = ra[0]; wa1 = ra[1]; wb0 = rb[0]; wb1 = rb[1];
            } else {
                wa0 = sBM2[chunk * 2]; wa1 = sBM2[chunk * 2 + 1];
                wb0 = wa0; wb1 = wa1;
            }
            float cm0 = -1e30f, cm1 = -1e30f;
#pragma unroll
            for (int nf = 0; nf < 8; nf++) {
                const int sh = (nf & 3) * 8 + qc * 2;
                const uint32_t ba = ((nf < 4 ? wa0 : wa1) >> sh);
                const uint32_t bb = ((nf < 4 ? wb0 : wb1) >> sh);
                s[nf][0] = (ba & 1u) ? s[nf][0] : -1e9f;
                s[nf][1] = (ba & 2u) ? s[nf][1] : -1e9f;
                s[nf][2] = (bb & 1u) ? s[nf][2] : -1e9f;
                s[nf][3] = (bb & 2u) ? s[nf][3] : -1e9f;
                cm0 = fmaxf(cm0, fmaxf(s[nf][0], s[nf][1]));
                cm1 = fmaxf(cm1, fmaxf(s[nf][2], s[nf][3]));
            }
            cm0 = fmaxf(cm0, __shfl_xor_sync(0xffffffffu, cm0, 1));
            cm0 = fmaxf(cm0, __shfl_xor_sync(0xffffffffu, cm0, 2));
            cm1 = fmaxf(cm1, __shfl_xor_sync(0xffffffffu, cm1, 1));
            cm1 = fmaxf(cm1, __shfl_xor_sync(0xffffffffu, cm1, 2));

            const float mn0 = fmaxf(m0, cm0), mn1 = fmaxf(m1, cm1);
            const float f0 = ex2f(m0 - mn0), f1 = ex2f(m1 - mn1);
            m0 = mn0; m1 = mn1;
            l0 *= f0; l1 *= f1;
#pragma unroll
            for (int n = 0; n < 4; n++) {
                o[n][0] *= f0; o[n][1] *= f0;
                o[n][2] *= f1; o[n][3] *= f1;
            }

#pragma unroll
            for (int nf = 0; nf < 8; nf++) {
                s[nf][0] = ex2f(s[nf][0] - mn0);
                s[nf][1] = ex2f(s[nf][1] - mn0);
                s[nf][2] = ex2f(s[nf][2] - mn1);
                s[nf][3] = ex2f(s[nf][3] - mn1);
                l0 += s[nf][0] + s[nf][1];
                l1 += s[nf][2] + s[nf][3];
            }

#pragma unroll
            for (int j = 0; j < 4; j++) {
                uint32_t ap[4];
                ap[0] = f22u(s[2*j][0],   s[2*j][1]);
                ap[1] = f22u(s[2*j][2],   s[2*j][3]);
                ap[2] = f22u(s[2*j+1][0], s[2*j+1][1]);
                ap[3] = f22u(s[2*j+1][2], s[2*j+1][3]);
                const __half* vbase = sV + (size_t)(key0 + j * 16 + arow) * KPADH + acol;
                uint32_t vb0[4], vb1[4];
                ldsm4t(vb0, vbase);
                ldsm4t(vb1, vbase + 16);
                mma16816(o[0], ap, vb0 + 0);
                mma16816(o[1], ap, vb0 + 2);
                mma16816(o[2], ap, vb1 + 0);
                mma16816(o[3], ap, vb1 + 2);
            }
        }

        l0 += __shfl_xor_sync(0xffffffffu, l0, 1);
        l0 += __shfl_xor_sync(0xffffffffu, l0, 2);
        l1 += __shfl_xor_sync(0xffffffffu, l1, 1);
        l1 += __shfl_xor_sync(0xffffffffu, l1, 2);
        const float i0 = 1.0f / l0, i1 = 1.0f / l1;
#pragma unroll
        for (int n = 0; n < 4; n++) {
            ofin[n][0] += o[n][0] * i0;
            ofin[n][1] += o[n][1] * i0;
            ofin[n][2] += o[n][2] * i1;
            ofin[n][3] += o[n][3] * i1;
        }
    }

    __half* outA = ctx + (size_t)(b * CN1 + q0 + warp * 16 + qr) * CD + h * CDH + qc * 2;
    __half* outB = outA + 8 * CD;
#pragma unroll
    for (int n = 0; n < 4; n++) {
        *(uint32_t*)(outA + n * 8) = f22u(ofin[n][0], ofin[n][1]);
        *(uint32_t*)(outB + n * 8) = f22u(ofin[n][2], ofin[n][3]);
    }
}

// ============================================================================
// LayerNorm variants (exact R15)
// ============================================================================
template <int XH, int WF, int WHm>
__global__ __launch_bounds__(256)
void add_ln_kernel(const void* __restrict__ Xv, const __half* __restrict__ Y,
                   const float* __restrict__ g, const float* __restrict__ be,
                   float* __restrict__ outF, __half* __restrict__ outH)
{
    const int warp = threadIdx.x >> 5;
    const int lane = threadIdx.x & 31;
    const size_t row = (size_t)blockIdx.x * 8 + warp;
    float v[8];
    float s = 0.0f;
#pragma unroll
    for (int i = 0; i < 8; i++) {
        int c = lane + i * 32;
        float xv = XH ? __half2float(((const __half*)Xv)[row * CD + c])
                      : ((const float*)Xv)[row * CD + c];
        v[i] = xv + __half2float(Y[row * CD + c]);
        s += v[i];
    }
#pragma unroll
    for (int o = 16; o > 0; o >>= 1) s += __shfl_xor_sync(0xffffffffu, s, o);
    const float mu = s * (1.0f / CD);
    float s2 = 0.0f;
#pragma unroll
    for (int i = 0; i < 8; i++) { float d = v[i] - mu; s2 += d * d; }
#pragma unroll
    for (int o = 16; o > 0; o >>= 1) s2 += __shfl_xor_sync(0xffffffffu, s2, o);
    const float inv = rsqrtf(s2 * (1.0f / CD) + 1e-6f);
#pragma unroll
    for (int i = 0; i < 8; i++) {
        int c = lane + i * 32;
        float r = g[c] * (v[i] - mu) * inv + be[c];
        if (WF)  outF[row * CD + c] = r;
        if (WHm) outH[row * CD + c] = __float2half(r);
    }
}

// ============================================================================
// Unified prep kernel: weight transpose+cvt | x->half + bias | mask bitmaps.
// blockIdx.x ranges:  [0,6144) weights, [6144,38912) misc, [38912,43136) bm.
// 256 threads everywhere; math identical to the three R15 kernels.
// ============================================================================
#define PREP_W   6144
#define PREP_MI  (PREP_W + 32768)
#define PREP_TOT (PREP_MI + 4224)

__global__ __launch_bounds__(256)
void prep_kernel(const float* __restrict__ Wq, const float* __restrict__ Wk,
                 const float* __restrict__ Wv, const float* __restrict__ Wo,
                 const float* __restrict__ W1, const float* __restrict__ W2,
                 __half* __restrict__ wqkvT, __half* __restrict__ woT,
                 __half* __restrict__ w1T,  __half* __restrict__ w2T,
                 const float* __restrict__ x1, const float* __restrict__ x2,
                 const float* __restrict__ bq, const float* __restrict__ bk,
                 const float* __restrict__ bv,
                 __half* __restrict__ x1h, __half* __restrict__ x2h,
                 float* __restrict__ bqkv,
                 const float* __restrict__ adj, const float* __restrict__ mask1,
                 const float* __restrict__ mask2,
                 uint32_t* __restrict__ bm1, uint32_t* __restrict__ bm2)
{
    const int bid = blockIdx.x;

    if (bid < PREP_W) {
        // ---- weight transpose: z = bid/1024, gy = (bid%1024)/32, gx = bid%32
        __shared__ float tile[32][33];
        const int z  = bid >> 10;
        const int gy = (bid & 1023) >> 5;
        const int gx = bid & 31;
        const float* src; __half* dst; int K, N; float scale = 1.0f;
        switch (z) {
            case 0: src = Wq; dst = wqkvT;            K = CD;   N = CD;   scale = QSCALE; break;
            case 1: src = Wk; dst = wqkvT + 256 * CD; K = CD;   N = CD;   break;
            case 2: src = Wv; dst = wqkvT + 512 * CD; K = CD;   N = CD;   break;
            case 3: src = Wo; dst = woT;              K = CD;   N = CD;   break;
            case 4: src = W1; dst = w1T;              K = CD;   N = CDFF; break;
            default: src = W2; dst = w2T;             K = CDFF; N = CD;   break;
        }
        const int k0 = gy * 32, n0 = gx * 32;
        if (k0 >= K || n0 >= N) return;
        const int tx = threadIdx.x & 31, ty = threadIdx.x >> 5;
#pragma unroll
        for (int i = 0; i < 32; i += 8)
            tile[ty + i][tx] = src[(size_t)(k0 + ty + i) * N + n0 + tx];
        __syncthreads();
#pragma unroll
        for (int i = 0; i < 32; i += 8)
            dst[(size_t)(n0 + ty + i) * K + k0 + tx] = __float2half(tile[tx][ty + i] * scale);
        return;
    }

    if (bid < PREP_MI) {
        // ---- x -> half, bias concat
        const size_t i = (size_t)(bid - PREP_W) * 256 + threadIdx.x;
        x1h[i] = __float2half(x1[i]);
        x2h[i] = __float2half(x2[i]);
        if (i < 256) {
            bqkv[i]       = bq[i] * QSCALE;
            bqkv[256 + i] = bk[i];
            bqkv[512 + i] = bv[i];
        }
        return;
    }

    // ---- mask bitmaps
    const int mb = bid - PREP_MI;          // 0..4223
    const int lane = threadIdx.x & 31;
    if (mb < 4096) {
        const int gw = (mb * 256 + threadIdx.x) >> 5;
        const int b = gw >> 8;
        const float* arow = adj + (size_t)gw * 256;
        const float* m1 = mask1 + (size_t)b * 256;
#pragma unroll
        for (int w = 0; w < 8; w++) {
            float v = arow[w * 32 + lane] * m1[w * 32 + lane];
            uint32_t bits = __ballot_sync(0xffffffffu, v > 0.0f);
            if (lane == 0) bm1[(size_t)gw * 8 + w] = bits;
        }
    } else {
        const int b = mb - 4096;
        const int w = threadIdx.x >> 5;
        float v = mask2[(size_t)b * 256 + w * 32 + lane];
        uint32_t bits = __ballot_sync(0xffffffffu, v > 0.0f);
        if (lane == 0) bm2[b * 8 + w] = bits;
    }
}

// ============================================================================
// Host launch
// ============================================================================
extern "C" void kernel_launch(void* const* d_in, const int* in_sizes, int n_in,
                              void* d_out, int out_size)
{
    const float* x1    = (const float*)d_in[0];
    const float* adj1  = (const float*)d_in[1];
    const float* mask1 = (const float*)d_in[2];
    const float* x2    = (const float*)d_in[3];
    const float* mask2 = (const float*)d_in[4];
    const float* Wq = (const float*)d_in[5];  const float* bq = (const float*)d_in[6];
    const float* Wk = (const float*)d_in[7];  const float* bk = (const float*)d_in[8];
    const float* Wv = (const float*)d_in[9];  const float* bv = (const float*)d_in[10];
    const float* Wo = (const float*)d_in[11]; const float* bo = (const float*)d_in[12];
    const float* W1 = (const float*)d_in[13]; const float* b1 = (const float*)d_in[14];
    const float* W2 = (const float*)d_in[15]; const float* b2 = (const float*)d_in[16];
    const float* g1 = (const float*)d_in[17]; const float* be1 = (const float*)d_in[18];
    const float* g2 = (const float*)d_in[19]; const float* be2 = (const float*)d_in[20];
    float* out = (float*)d_out;

    __half *wqkvT, *woT, *w1T, *w2T, *x1h, *x2h, *qkv, *kv2, *ctx, *tmph, *o1h, *hid;
    float *bqkv;
    uint32_t *bm1, *bm2;
    cudaGetSymbolAddress((void**)&wqkvT, g_wqkvT);
    cudaGetSymbolAddress((void**)&woT,   g_woT);
    cudaGetSymbolAddress((void**)&w1T,   g_w1T);
    cudaGetSymbolAddress((void**)&w2T,   g_w2T);
    cudaGetSymbolAddress((void**)&bqkv,  g_bqkv);
    cudaGetSymbolAddress((void**)&x1h,   g_x1h);
    cudaGetSymbolAddress((void**)&x2h,   g_x2h);
    cudaGetSymbolAddress((void**)&qkv,   g_qkv);
    cudaGetSymbolAddress((void**)&kv2,   g_kv2);
    cudaGetSymbolAddress((void**)&ctx,   g_ctx);
    cudaGetSymbolAddress((void**)&tmph,  g_tmph);
    cudaGetSymbolAddress((void**)&o1h,   g_o1h);
    cudaGetSymbolAddress((void**)&hid,   g_hid);
    cudaGetSymbolAddress((void**)&bm1,   g_bm1);
    cudaGetSymbolAddress((void**)&bm2,   g_bm2);

    cudaFuncSetAttribute(proj_kernel, cudaFuncAttributeMaxDynamicSharedMemorySize, GSMEM_BYTES);
    cudaFuncSetAttribute(gemm_h<0,1>, cudaFuncAttributeMaxDynamicSharedMemorySize, GSMEM_BYTES);
    cudaFuncSetAttribute(gemm_h<1,1>, cudaFuncAttributeMaxDynamicSharedMemorySize, GSMEM_BYTES);
    cudaFuncSetAttribute(attn_kernel, cudaFuncAttributeMaxDynamicSharedMemorySize, ATT_SMEM_BYTES);

    const int M = CB * CN1;

    // unified prep (weights + x->half + bitmasks) in ONE launch
    prep_kernel<<<PREP_TOT, 256>>>(Wq, Wk, Wv, Wo, W1, W2,
                                   wqkvT, woT, w1T, w2T,
                                   x1, x2, bq, bk, bv, x1h, x2h, bqkv,
                                   adj1, mask1, mask2, bm1, bm2);

    // merged qkv + kv2 projection (2560 CTAs)
    proj_kernel<<<dim3(10, M / BM), 128, GSMEM_BYTES>>>(x1h, x2h, wqkvT, bqkv, qkv, kv2);

    attn_kernel<<<dim3(CN1 / 128, CH, CB), 256, ATT_SMEM_BYTES>>>(qkv, kv2, bm1, bm2, ctx);

    // wo projection -> half tmp; LN1: X = x1 (fp32), Y = tmph -> o1h only
    gemm_h<0,1><<<dim3(2, M / BM), 128, GSMEM_BYTES>>>(ctx, woT, bo, tmph, CD, CD);
    add_ln_kernel<0,0,1><<<M / 8, 256>>>(x1, tmph, g1, be1, nullptr, o1h);

    // FFN (half throughout); LN2: X = o1h (half), Y = tmph -> fp32 out
    gemm_h<1,1><<<dim3(8, M / BM), 128, GSMEM_BYTES>>>(o1h, w1T, b1, hid, CDFF, CD);
    gemm_h<0,1><<<dim3(2, M / BM), 128, GSMEM_BYTES>>>(hid, w2T, b2, tmph, CD, CDFF);
    add_ln_kernel<1,1,0><<<M / 8, 256>>>(o1h, tmph, g2, be2, out, nullptr);
}

// round 17
// speedup vs baseline: 1.1630x; 1.0310x over previous
#include <cuda_runtime.h>
#include <cuda_fp16.h>
#include <cstdint>

#define CB   128
#define CN1  256
#define CN2  256
#define CD   256
#define CH   8
#define CDH  32
#define CDFF 1024

// ---------------- scratch (device globals) ----------------
__device__ __half g_wqkvT[768 * CD];      // [N][K] half, q-part pre-scaled
__device__ __half g_woT  [CD * CD];
__device__ __half g_w1T  [CDFF * CD];
__device__ __half g_w2T  [CD * CDFF];
__device__ float  g_bqkv [768];
__device__ __half g_x1h  [CB * CN1 * CD];
__device__ __half g_x2h  [CB * CN2 * CD];
__device__ __half g_qkv  [CB * CN1 * 768];
__device__ __half g_kv2  [CB * CN2 * 512];
__device__ __half g_ctx  [CB * CN1 * CD];
__device__ __half g_tmph [CB * CN1 * CD];
__device__ __half g_o1h  [CB * CN1 * CD];
__device__ __half g_hid  [CB * CN1 * CDFF];
__device__ uint32_t g_bm1[CB * CN1 * 8];
__device__ uint32_t g_bm2[CB * 8];

#define QSCALE (0.17677669529663687f * 1.4426950408889634f)

// ---------------- helpers ----------------
__device__ __forceinline__ void cp16(void* s, const void* g) {
    unsigned sa = (unsigned)__cvta_generic_to_shared(s);
    asm volatile("cp.async.cg.shared.global [%0], [%1], 16;\n" :: "r"(sa), "l"(g));
}
__device__ __forceinline__ void cp_commit() { asm volatile("cp.async.commit_group;\n"); }
template <int N> __device__ __forceinline__ void cp_wait() {
    asm volatile("cp.async.wait_group %0;\n" :: "n"(N));
}
__device__ __forceinline__ void mma16816(float* d, const uint32_t* a, const uint32_t* b) {
    asm volatile(
        "mma.sync.aligned.m16n8k16.row.col.f32.f16.f16.f32 "
        "{%0,%1,%2,%3}, {%4,%5,%6,%7}, {%8,%9}, {%0,%1,%2,%3};"
        : "+f"(d[0]), "+f"(d[1]), "+f"(d[2]), "+f"(d[3])
        : "r"(a[0]), "r"(a[1]), "r"(a[2]), "r"(a[3]), "r"(b[0]), "r"(b[1]));
}
__device__ __forceinline__ void ldsm4(uint32_t* r, const __half* p) {
    uint32_t a = (uint32_t)__cvta_generic_to_shared(p);
    asm volatile("ldmatrix.sync.aligned.m8n8.x4.shared.b16 {%0,%1,%2,%3}, [%4];"
                 : "=r"(r[0]), "=r"(r[1]), "=r"(r[2]), "=r"(r[3]) : "r"(a));
}
__device__ __forceinline__ void ldsm4t(uint32_t* r, const __half* p) {
    uint32_t a = (uint32_t)__cvta_generic_to_shared(p);
    asm volatile("ldmatrix.sync.aligned.m8n8.x4.trans.shared.b16 {%0,%1,%2,%3}, [%4];"
                 : "=r"(r[0]), "=r"(r[1]), "=r"(r[2]), "=r"(r[3]) : "r"(a));
}
__device__ __forceinline__ float ex2f(float x) {
    float y; asm("ex2.approx.f32 %0, %1;" : "=f"(y) : "f"(x)); return y;
}
__device__ __forceinline__ uint32_t f22u(float a, float b) {
    __half2 h = __floats2half2_rn(a, b);
    return *(uint32_t*)&h;
}

// ============================================================================
// fp16 GEMM body (exact R14/R15/R16): block 128x128x64, 4 warps, warp 64x64,
// m16n8k16, ldmatrix, 3-stage cp.async (depth-2 prefetch), runtime N/K.
// ============================================================================
#define BM 128
#define BN 128
#define BK 64
#define APADH 72
#define STGH (2 * 128 * APADH)
#define GS 3
#define GSMEM_BYTES (GS * STGH * 2)               // 110592

template <int EPI, int OUTH>
__device__ __forceinline__ void gemm_body(
    const __half* __restrict__ A, const __half* __restrict__ WT,
    const float* __restrict__ bias, void* __restrict__ Cv,
    __half* smh, int m0, int n0, int N, int K, int tid)
{
    const int warp = tid >> 5;
    const int lane = tid & 31;
    const int wm   = warp & 1;
    const int wn   = warp >> 1;
    const int kt   = K / BK;
    const int qr   = lane >> 2;
    const int qc   = lane & 3;
    const int arow = (lane & 7) + 8 * ((lane >> 3) & 1);
    const int acol = 8 * (lane >> 4);
    const int brow = (lane & 7) + 8 * (lane >> 4);
    const int bcol = 8 * ((lane >> 3) & 1);

    auto stageSlot = [&](int t) -> __half* {
        int s = t % GS;
        return smh + s * STGH;
    };

    auto loadStage = [&](int t) {
        __half* As = stageSlot(t);
        __half* Bs = As + 128 * APADH;
        const int k0 = t * BK;
#pragma unroll
        for (int j = 0; j < 8; j++) {
            int i = tid + j * 128;
            int r = i >> 3, c8 = (i & 7) * 8;
            cp16(As + r * APADH + c8, A + (size_t)(m0 + r) * K + k0 + c8);
        }
#pragma unroll
        for (int j = 0; j < 8; j++) {
            int i = tid + j * 128;
            int r = i >> 3, c8 = (i & 7) * 8;
            cp16(Bs + r * APADH + c8, WT + (size_t)(n0 + r) * K + k0 + c8);
        }
        cp_commit();
    };

    float acc[4][8][4];
#pragma unroll
    for (int mt = 0; mt < 4; mt++)
#pragma unroll
        for (int nt = 0; nt < 8; nt++)
#pragma unroll
            for (int e = 0; e < 4; e++) acc[mt][nt][e] = 0.0f;

    loadStage(0);
    loadStage(1);

    for (int t = 0; t < kt; t++) {
        if (t + 1 < kt) cp_wait<1>(); else cp_wait<0>();
        __syncthreads();
        if (t + 2 < kt) loadStage(t + 2);

        const __half* As = stageSlot(t) + (wm * 64) * APADH;
        const __half* Bs = stageSlot(t) + 128 * APADH + (wn * 64) * APADH;
#pragma unroll
        for (int kk = 0; kk < BK; kk += 16) {
            uint32_t af[4][4];
            uint32_t bf[4][4];
#pragma unroll
            for (int mt = 0; mt < 4; mt++)
                ldsm4(af[mt], As + (mt * 16 + arow) * APADH + kk + acol);
#pragma unroll
            for (int p = 0; p < 4; p++)
                ldsm4(bf[p], Bs + (p * 16 + brow) * APADH + kk + bcol);
#pragma unroll
            for (int mt = 0; mt < 4; mt++)
#pragma unroll
                for (int nt = 0; nt < 8; nt++)
                    mma16816(acc[mt][nt], af[mt], &bf[nt >> 1][(nt & 1) * 2]);
        }
    }

    // register -> global epilogue
#pragma unroll
    for (int nt = 0; nt < 8; nt++) {
        const int col = n0 + wn * 64 + nt * 8 + qc * 2;
        const float2 bv = *(const float2*)(bias + col);
#pragma unroll
        for (int mt = 0; mt < 4; mt++) {
            const int row = m0 + wm * 64 + mt * 16 + qr;
            float a0 = acc[mt][nt][0] + bv.x, a1 = acc[mt][nt][1] + bv.y;
            float a2 = acc[mt][nt][2] + bv.x, a3 = acc[mt][nt][3] + bv.y;
            if (EPI == 1) {
                a0 = fmaxf(a0, 0.f); a1 = fmaxf(a1, 0.f);
                a2 = fmaxf(a2, 0.f); a3 = fmaxf(a3, 0.f);
            }
            if (OUTH) {
                __half* C = (__half*)Cv;
                *(uint32_t*)(C + (size_t)row * N + col)       = f22u(a0, a1);
                *(uint32_t*)(C + (size_t)(row + 8) * N + col) = f22u(a2, a3);
            } else {
                float* C = (float*)Cv;
                *(float2*)(C + (size_t)row * N + col)       = make_float2(a0, a1);
                *(float2*)(C + (size_t)(row + 8) * N + col) = make_float2(a2, a3);
            }
        }
    }
}

// merged qkv + kv2 projection: grid.x = 10 (6 qkv tiles + 4 kv2 tiles)
__global__ __launch_bounds__(128, 2)
void proj_kernel(const __half* __restrict__ x1h, const __half* __restrict__ x2h,
                 const __half* __restrict__ wqkvT, const float* __restrict__ bqkv,
                 __half* __restrict__ qkv, __half* __restrict__ kv2)
{
    extern __shared__ __half smh[];
    const int bx = blockIdx.x;
    const int m0 = blockIdx.y * BM;
    if (bx < 6)
        gemm_body<0, 1>(x1h, wqkvT, bqkv, qkv, smh, m0, bx * 128, 768, 256, threadIdx.x);
    else
        gemm_body<0, 1>(x2h, wqkvT + 256 * CD, bqkv + 256, kv2, smh,
                        m0, (bx - 6) * 128, 512, 256, threadIdx.x);
}

template <int EPI, int OUTH>
__global__ __launch_bounds__(128, 2)
void gemm_h(const __half* __restrict__ A, const __half* __restrict__ WT,
            const float* __restrict__ bias, void* __restrict__ Cv, int N, int K)
{
    extern __shared__ __half smh[];
    gemm_body<EPI, OUTH>(A, WT, bias, Cv, smh,
                         blockIdx.y * BM, blockIdx.x * BN, N, K, threadIdx.x);
}

// ============================================================================
// FlashAttention-style dual-source graph attention.
// R17: BOTH sources' K/V preloaded via cp.async up front; Q frags + bitmask
// staging overlap the async copies; single barrier; no mid-kernel syncs.
// ============================================================================
#define KPADH 40
#define TILE_H   (256 * KPADH)                       // halves per K or V tile
#define ATT_BM_OFF (4 * TILE_H * 2)                  // bytes: 4 tiles (K0,V0,K1,V1)
#define ATT_SMEM_BYTES (ATT_BM_OFF + (1024 + 8) * 4) // 86048

__global__ __launch_bounds__(256, 2)
void attn_kernel(const __half* __restrict__ qkv, const __half* __restrict__ kv2,
                 const uint32_t* __restrict__ bm1, const uint32_t* __restrict__ bm2,
                 __half* __restrict__ ctx)
{
    extern __shared__ __half smh[];
    // layout: [K0][V0][K1][V1][bm1 tile][bm2]
    uint32_t* sBM  = (uint32_t*)((char*)smh + ATT_BM_OFF);
    uint32_t* sBM2 = sBM + 1024;

    const int b  = blockIdx.z;
    const int h  = blockIdx.y;
    const int q0 = blockIdx.x * 128;
    const int tid  = threadIdx.x;
    const int warp = tid >> 5;
    const int lane = tid & 31;
    const int qr   = lane >> 2;
    const int qc   = lane & 3;
    const int arow = (lane & 7) + 8 * ((lane >> 3) & 1);
    const int acol = 8 * (lane >> 4);
    const int brow = (lane & 7) + 8 * (lane >> 4);
    const int bcol = 8 * ((lane >> 3) & 1);

    // ---- issue cp.async for BOTH sources' K and V tiles (no waits yet) ----
#pragma unroll
    for (int src = 0; src < 2; src++) {
        const __half* base = src ? kv2 : qkv;
        const int stride  = src ? 512 : 768;
        const int koff    = src ? 0   : 256;
        const int voff    = src ? 256 : 512;
        __half* sK = smh + (size_t)(2 * src) * TILE_H;
        __half* sV = sK + TILE_H;
#pragma unroll
        for (int j = 0; j < 4; j++) {
            int i = tid + j * 256;
            int r = i >> 2, c8 = (i & 3) * 8;
            const __half* row = base + (size_t)(b * 256 + r) * stride + h * CDH;
            cp16(sK + r * KPADH + c8, row + koff + c8);
            cp16(sV + r * KPADH + c8, row + voff + c8);
        }
    }
    cp_commit();

    // ---- overlap: bitmasks to smem + Q fragments from global ----
#pragma unroll
    for (int j = 0; j < 4; j++) {
        int i = tid + j * 256;
        sBM[i] = bm1[((size_t)(b * CN1) + q0 + (i >> 3)) * 8 + (i & 7)];
    }
    if (tid < 8) sBM2[tid] = bm2[b * 8 + tid];

    uint32_t qf[2][4];
    {
        const __half* Qb = qkv + (size_t)(b * CN1 + q0 + warp * 16) * 768 + h * CDH;
#pragma unroll
        for (int kc = 0; kc < 2; kc++) {
            const __half* p = Qb + kc * 16 + 2 * qc;
            qf[kc][0] = *(const uint32_t*)(p + (size_t)qr * 768);
            qf[kc][1] = *(const uint32_t*)(p + (size_t)(qr + 8) * 768);
            qf[kc][2] = *(const uint32_t*)(p + (size_t)qr * 768 + 8);
            qf[kc][3] = *(const uint32_t*)(p + (size_t)(qr + 8) * 768 + 8);
        }
    }

    cp_wait<0>();
    __syncthreads();          // the only barrier in the kernel

    float ofin[4][4];
#pragma unroll
    for (int n = 0; n < 4; n++)
#pragma unroll
        for (int e = 0; e < 4; e++) ofin[n][e] = 0.0f;

#pragma unroll 1
    for (int src = 0; src < 2; src++) {
        const __half* sK = smh + (size_t)(2 * src) * TILE_H;
        const __half* sV = sK + TILE_H;

        float m0 = -1e30f, m1 = -1e30f, l0 = 0.0f, l1 = 0.0f;
        float o[4][4];
#pragma unroll
        for (int n = 0; n < 4; n++)
#pragma unroll
            for (int e = 0; e < 4; e++) o[n][e] = 0.0f;

#pragma unroll 1
        for (int chunk = 0; chunk < 4; chunk++) {
            const int key0 = chunk * 64;

            float s[8][4];
#pragma unroll
            for (int nf = 0; nf < 8; nf++)
                s[nf][0] = s[nf][1] = s[nf][2] = s[nf][3] = 0.0f;
#pragma unroll
            for (int pr = 0; pr < 4; pr++) {
                const __half* kbase = sK + (size_t)(key0 + pr * 16 + brow) * KPADH + bcol;
                uint32_t kb0[4], kb1[4];
                ldsm4(kb0, kbase);
                ldsm4(kb1, kbase + 16);
                mma16816(s[2 * pr],     qf[0], kb0 + 0);
                mma16816(s[2 * pr],     qf[1], kb1 + 0);
                mma16816(s[2 * pr + 1], qf[0], kb0 + 2);
                mma16816(s[2 * pr + 1], qf[1], kb1 + 2);
            }

            uint32_t wa0, wa1, wb0, wb1;
            if (src == 0) {
                const uint32_t* ra = sBM + (warp * 16 + qr) * 8 + chunk * 2;
                const uint32_t* rb = sBM + (warp * 16 + qr + 8) * 8 + chunk * 2;
                wa0 = ra[0]; wa1 = ra[1]; wb0 = rb[0]; wb1 = rb[1];
            } else {
                wa0 = sBM2[chunk * 2]; wa1 = sBM2[chunk * 2 + 1];
                wb0 = wa0; wb1 = wa1;
            }
            float cm0 = -1e30f, cm1 = -1e30f;
#pragma unroll
            for (int nf = 0; nf < 8; nf++) {
                const int sh = (nf & 3) * 8 + qc * 2;
                const uint32_t ba = ((nf < 4 ? wa0 : wa1) >> sh);
                const uint32_t bb = ((nf < 4 ? wb0 : wb1) >> sh);
                s[nf][0] = (ba & 1u) ? s[nf][0] : -1e9f;
                s[nf][1] = (ba & 2u) ? s[nf][1] : -1e9f;
                s[nf][2] = (bb & 1u) ? s[nf][2] : -1e9f;
                s[nf][3] = (bb & 2u) ? s[nf][3] : -1e9f;
                cm0 = fmaxf(cm0, fmaxf(s[nf][0], s[nf][1]));
                cm1 = fmaxf(cm1, fmaxf(s[nf][2], s[nf][3]));
            }
            cm0 = fmaxf(cm0, __shfl_xor_sync(0xffffffffu, cm0, 1));
            cm0 = fmaxf(cm0, __shfl_xor_sync(0xffffffffu, cm0, 2));
            cm1 = fmaxf(cm1, __shfl_xor_sync(0xffffffffu, cm1, 1));
            cm1 = fmaxf(cm1, __shfl_xor_sync(0xffffffffu, cm1, 2));

            const float mn0 = fmaxf(m0, cm0), mn1 = fmaxf(m1, cm1);
            const float f0 = ex2f(m0 - mn0), f1 = ex2f(m1 - mn1);
            m0 = mn0; m1 = mn1;
            l0 *= f0; l1 *= f1;
#pragma unroll
            for (int n = 0; n < 4; n++) {
                o[n][0] *= f0; o[n][1] *= f0;
                o[n][2] *= f1; o[n][3] *= f1;
            }

#pragma unroll
            for (int nf = 0; nf < 8; nf++) {
                s[nf][0] = ex2f(s[nf][0] - mn0);
                s[nf][1] = ex2f(s[nf][1] - mn0);
                s[nf][2] = ex2f(s[nf][2] - mn1);
                s[nf][3] = ex2f(s[nf][3] - mn1);
                l0 += s[nf][0] + s[nf][1];
                l1 += s[nf][2] + s[nf][3];
            }

#pragma unroll
            for (int j = 0; j < 4; j++) {
                uint32_t ap[4];
                ap[0] = f22u(s[2*j][0],   s[2*j][1]);
                ap[1] = f22u(s[2*j][2],   s[2*j][3]);
                ap[2] = f22u(s[2*j+1][0], s[2*j+1][1]);
                ap[3] = f22u(s[2*j+1][2], s[2*j+1][3]);
                const __half* vbase = sV + (size_t)(key0 + j * 16 + arow) * KPADH + acol;
                uint32_t vb0[4], vb1[4];
                ldsm4t(vb0, vbase);
                ldsm4t(vb1, vbase + 16);
                mma16816(o[0], ap, vb0 + 0);
                mma16816(o[1], ap, vb0 + 2);
                mma16816(o[2], ap, vb1 + 0);
                mma16816(o[3], ap, vb1 + 2);
            }
        }

        l0 += __shfl_xor_sync(0xffffffffu, l0, 1);
        l0 += __shfl_xor_sync(0xffffffffu, l0, 2);
        l1 += __shfl_xor_sync(0xffffffffu, l1, 1);
        l1 += __shfl_xor_sync(0xffffffffu, l1, 2);
        const float i0 = 1.0f / l0, i1 = 1.0f / l1;
#pragma unroll
        for (int n = 0; n < 4; n++) {
            ofin[n][0] += o[n][0] * i0;
            ofin[n][1] += o[n][1] * i0;
            ofin[n][2] += o[n][2] * i1;
            ofin[n][3] += o[n][3] * i1;
        }
    }

    __half* outA = ctx + (size_t)(b * CN1 + q0 + warp * 16 + qr) * CD + h * CDH + qc * 2;
    __half* outB = outA + 8 * CD;
#pragma unroll
    for (int n = 0; n < 4; n++) {
        *(uint32_t*)(outA + n * 8) = f22u(ofin[n][0], ofin[n][1]);
        *(uint32_t*)(outB + n * 8) = f22u(ofin[n][2], ofin[n][3]);
    }
}

// ============================================================================
// LayerNorm variants (exact R15/R16)
// ============================================================================
template <int XH, int WF, int WHm>
__global__ __launch_bounds__(256)
void add_ln_kernel(const void* __restrict__ Xv, const __half* __restrict__ Y,
                   const float* __restrict__ g, const float* __restrict__ be,
                   float* __restrict__ outF, __half* __restrict__ outH)
{
    const int warp = threadIdx.x >> 5;
    const int lane = threadIdx.x & 31;
    const size_t row = (size_t)blockIdx.x * 8 + warp;
    float v[8];
    float s = 0.0f;
#pragma unroll
    for (int i = 0; i < 8; i++) {
        int c = lane + i * 32;
        float xv = XH ? __half2float(((const __half*)Xv)[row * CD + c])
                      : ((const float*)Xv)[row * CD + c];
        v[i] = xv + __half2float(Y[row * CD + c]);
        s += v[i];
    }
#pragma unroll
    for (int o = 16; o > 0; o >>= 1) s += __shfl_xor_sync(0xffffffffu, s, o);
    const float mu = s * (1.0f / CD);
    float s2 = 0.0f;
#pragma unroll
    for (int i = 0; i < 8; i++) { float d = v[i] - mu; s2 += d * d; }
#pragma unroll
    for (int o = 16; o > 0; o >>= 1) s2 += __shfl_xor_sync(0xffffffffu, s2, o);
    const float inv = rsqrtf(s2 * (1.0f / CD) + 1e-6f);
#pragma unroll
    for (int i = 0; i < 8; i++) {
        int c = lane + i * 32;
        float r = g[c] * (v[i] - mu) * inv + be[c];
        if (WF)  outF[row * CD + c] = r;
        if (WHm) outH[row * CD + c] = __float2half(r);
    }
}

// ============================================================================
// Unified prep kernel (exact R16)
// ============================================================================
#define PREP_W   6144
#define PREP_MI  (PREP_W + 32768)
#define PREP_TOT (PREP_MI + 4224)

__global__ __launch_bounds__(256)
void prep_kernel(const float* __restrict__ Wq, const float* __restrict__ Wk,
                 const float* __restrict__ Wv, const float* __restrict__ Wo,
                 const float* __restrict__ W1, const float* __restrict__ W2,
                 __half* __restrict__ wqkvT, __half* __restrict__ woT,
                 __half* __restrict__ w1T,  __half* __restrict__ w2T,
                 const float* __restrict__ x1, const float* __restrict__ x2,
                 const float* __restrict__ bq, const float* __restrict__ bk,
                 const float* __restrict__ bv,
                 __half* __restrict__ x1h, __half* __restrict__ x2h,
                 float* __restrict__ bqkv,
                 const float* __restrict__ adj, const float* __restrict__ mask1,
                 const float* __restrict__ mask2,
                 uint32_t* __restrict__ bm1, uint32_t* __restrict__ bm2)
{
    const int bid = blockIdx.x;

    if (bid < PREP_W) {
        __shared__ float tile[32][33];
        const int z  = bid >> 10;
        const int gy = (bid & 1023) >> 5;
        const int gx = bid & 31;
        const float* src; __half* dst; int K, N; float scale = 1.0f;
        switch (z) {
            case 0: src = Wq; dst = wqkvT;            K = CD;   N = CD;   scale = QSCALE; break;
            case 1: src = Wk; dst = wqkvT + 256 * CD; K = CD;   N = CD;   break;
            case 2: src = Wv; dst = wqkvT + 512 * CD; K = CD;   N = CD;   break;
            case 3: src = Wo; dst = woT;              K = CD;   N = CD;   break;
            case 4: src = W1; dst = w1T;              K = CD;   N = CDFF; break;
            default: src = W2; dst = w2T;             K = CDFF; N = CD;   break;
        }
        const int k0 = gy * 32, n0 = gx * 32;
        if (k0 >= K || n0 >= N) return;
        const int tx = threadIdx.x & 31, ty = threadIdx.x >> 5;
#pragma unroll
        for (int i = 0; i < 32; i += 8)
            tile[ty + i][tx] = src[(size_t)(k0 + ty + i) * N + n0 + tx];
        __syncthreads();
#pragma unroll
        for (int i = 0; i < 32; i += 8)
            dst[(size_t)(n0 + ty + i) * K + k0 + tx] = __float2half(tile[tx][ty + i] * scale);
        return;
    }

    if (bid < PREP_MI) {
        const size_t i = (size_t)(bid - PREP_W) * 256 + threadIdx.x;
        x1h[i] = __float2half(x1[i]);
        x2h[i] = __float2half(x2[i]);
        if (i < 256) {
            bqkv[i]       = bq[i] * QSCALE;
            bqkv[256 + i] = bk[i];
            bqkv[512 + i] = bv[i];
        }
        return;
    }

    const int mb = bid - PREP_MI;
    const int lane = threadIdx.x & 31;
    if (mb < 4096) {
        const int gw = (mb * 256 + threadIdx.x) >> 5;
        const int b = gw >> 8;
        const float* arow = adj + (size_t)gw * 256;
        const float* m1 = mask1 + (size_t)b * 256;
#pragma unroll
        for (int w = 0; w < 8; w++) {
            float v = arow[w * 32 + lane] * m1[w * 32 + lane];
            uint32_t bits = __ballot_sync(0xffffffffu, v > 0.0f);
            if (lane == 0) bm1[(size_t)gw * 8 + w] = bits;
        }
    } else {
        const int b = mb - 4096;
        const int w = threadIdx.x >> 5;
        float v = mask2[(size_t)b * 256 + w * 32 + lane];
        uint32_t bits = __ballot_sync(0xffffffffu, v > 0.0f);
        if (lane == 0) bm2[b * 8 + w] = bits;
    }
}

// ============================================================================
// Host launch
// ============================================================================
extern "C" void kernel_launch(void* const* d_in, const int* in_sizes, int n_in,
                              void* d_out, int out_size)
{
    const float* x1    = (const float*)d_in[0];
    const float* adj1  = (const float*)d_in[1];
    const float* mask1 = (const float*)d_in[2];
    const float* x2    = (const float*)d_in[3];
    const float* mask2 = (const float*)d_in[4];
    const float* Wq = (const float*)d_in[5];  const float* bq = (const float*)d_in[6];
    const float* Wk = (const float*)d_in[7];  const float* bk = (const float*)d_in[8];
    const float* Wv = (const float*)d_in[9];  const float* bv = (const float*)d_in[10];
    const float* Wo = (const float*)d_in[11]; const float* bo = (const float*)d_in[12];
    const float* W1 = (const float*)d_in[13]; const float* b1 = (const float*)d_in[14];
    const float* W2 = (const float*)d_in[15]; const float* b2 = (const float*)d_in[16];
    const float* g1 = (const float*)d_in[17]; const float* be1 = (const float*)d_in[18];
    const float* g2 = (const float*)d_in[19]; const float* be2 = (const float*)d_in[20];
    float* out = (float*)d_out;

    __half *wqkvT, *woT, *w1T, *w2T, *x1h, *x2h, *qkv, *kv2, *ctx, *tmph, *o1h, *hid;
    float *bqkv;
    uint32_t *bm1, *bm2;
    cudaGetSymbolAddress((void**)&wqkvT, g_wqkvT);
    cudaGetSymbolAddress((void**)&woT,   g_woT);
    cudaGetSymbolAddress((void**)&w1T,   g_w1T);
    cudaGetSymbolAddress((void**)&w2T,   g_w2T);
    cudaGetSymbolAddress((void**)&bqkv,  g_bqkv);
    cudaGetSymbolAddress((void**)&x1h,   g_x1h);
    cudaGetSymbolAddress((void**)&x2h,   g_x2h);
    cudaGetSymbolAddress((void**)&qkv,   g_qkv);
    cudaGetSymbolAddress((void**)&kv2,   g_kv2);
    cudaGetSymbolAddress((void**)&ctx,   g_ctx);
    cudaGetSymbolAddress((void**)&tmph,  g_tmph);
    cudaGetSymbolAddress((void**)&o1h,   g_o1h);
    cudaGetSymbolAddress((void**)&hid,   g_hid);
    cudaGetSymbolAddress((void**)&bm1,   g_bm1);
    cudaGetSymbolAddress((void**)&bm2,   g_bm2);

    cudaFuncSetAttribute(proj_kernel, cudaFuncAttributeMaxDynamicSharedMemorySize, GSMEM_BYTES);
    cudaFuncSetAttribute(gemm_h<0,1>, cudaFuncAttributeMaxDynamicSharedMemorySize, GSMEM_BYTES);
    cudaFuncSetAttribute(gemm_h<1,1>, cudaFuncAttributeMaxDynamicSharedMemorySize, GSMEM_BYTES);
    cudaFuncSetAttribute(attn_kernel, cudaFuncAttributeMaxDynamicSharedMemorySize, ATT_SMEM_BYTES);

    const int M = CB * CN1;

    prep_kernel<<<PREP_TOT, 256>>>(Wq, Wk, Wv, Wo, W1, W2,
                                   wqkvT, woT, w1T, w2T,
                                   x1, x2, bq, bk, bv, x1h, x2h, bqkv,
                                   adj1, mask1, mask2, bm1, bm2);

    proj_kernel<<<dim3(10, M / BM), 128, GSMEM_BYTES>>>(x1h, x2h, wqkvT, bqkv, qkv, kv2);

    attn_kernel<<<dim3(CN1 / 128, CH, CB), 256, ATT_SMEM_BYTES>>>(qkv, kv2, bm1, bm2, ctx);

    gemm_h<0,1><<<dim3(2, M / BM), 128, GSMEM_BYTES>>>(ctx, woT, bo, tmph, CD, CD);
    add_ln_kernel<0,0,1><<<M / 8, 256>>>(x1, tmph, g1, be1, nullptr, o1h);

    gemm_h<1,1><<<dim3(8, M / BM), 128, GSMEM_BYTES>>>(o1h, w1T, b1, hid, CDFF, CD);
    gemm_h<0,1><<<dim3(2, M / BM), 128, GSMEM_BYTES>>>(hid, w2T, b2, tmph, CD, CDFF);
    add_ln_kernel<1,1,0><<<M / 8, 256>>>(o1h, tmph, g2, be2, out, nullptr);
}